// round 4
// baseline (speedup 1.0000x reference)
#include <cuda_runtime.h>
#include <cuda_bf16.h>
#include <math.h>
#include <stdint.h>

#define SLEN   2048
#define DMODEL 1024
#define NH     16
#define HDIM   64
#define NLAYER 4
#define FFND   4096
#define OUTD   128
#define IND    64

// ======================= helpers =============================================
__device__ __forceinline__ uint32_t smem_u32(const void* p) {
    uint32_t a;
    asm("{ .reg .u64 t; cvta.to.shared.u64 t, %1; cvt.u32.u64 %0, t; }"
        : "=r"(a) : "l"(p));
    return a;
}
__device__ __forceinline__ void ldm_x4(uint32_t* r, uint32_t addr) {
    asm volatile("ldmatrix.sync.aligned.m8n8.x4.shared.b16 {%0,%1,%2,%3}, [%4];"
                 : "=r"(r[0]), "=r"(r[1]), "=r"(r[2]), "=r"(r[3]) : "r"(addr));
}
__device__ __forceinline__ void ldm_x2_trans(uint32_t* r, uint32_t addr) {
    asm volatile("ldmatrix.sync.aligned.m8n8.x2.trans.shared.b16 {%0,%1}, [%2];"
                 : "=r"(r[0]), "=r"(r[1]) : "r"(addr));
}
__device__ __forceinline__ void mma_bf16(float* c, const uint32_t* a, const uint32_t* b) {
    asm volatile(
        "mma.sync.aligned.m16n8k16.row.col.f32.bf16.bf16.f32 "
        "{%0,%1,%2,%3}, {%4,%5,%6,%7}, {%8,%9}, {%0,%1,%2,%3};"
        : "+f"(c[0]), "+f"(c[1]), "+f"(c[2]), "+f"(c[3])
        : "r"(a[0]), "r"(a[1]), "r"(a[2]), "r"(a[3]), "r"(b[0]), "r"(b[1]));
}
__device__ __forceinline__ void sts8(uint32_t addr, uint32_t a, uint32_t b) {
    asm volatile("st.shared.v2.b32 [%0], {%1,%2};" :: "r"(addr), "r"(a), "r"(b));
}
// hi/lo split of 2 floats packed into bf16x2 words
__device__ __forceinline__ void split2(float x, float y, uint32_t& h, uint32_t& l) {
    __nv_bfloat16 hx = __float2bfloat16(x), hy = __float2bfloat16(y);
    __nv_bfloat16 lx = __float2bfloat16(x - __bfloat162float(hx));
    __nv_bfloat16 ly = __float2bfloat16(y - __bfloat162float(hy));
    __nv_bfloat162 hp = __halves2bfloat162(hx, hy);
    __nv_bfloat162 lp = __halves2bfloat162(lx, ly);
    h = *reinterpret_cast<uint32_t*>(&hp);
    l = *reinterpret_cast<uint32_t*>(&lp);
}

// ======================= scratch =============================================
__device__ float g_h [SLEN * DMODEL];
__device__ float g_hn[SLEN * DMODEL];
__device__ float g_q [SLEN * DMODEL];
__device__ float g_k [SLEN * DMODEL];
__device__ float g_v [SLEN * DMODEL];
__device__ float g_o [SLEN * DMODEL];
__device__ float g_f1[SLEN * FFND];
__device__ float g_f3[SLEN * FFND];

// ============ HMMA GEMM: C[M,N] = A[M,K] @ B[K,N] (+bias)(+res) ==============
// A fp32 row-major [M,K], B fp32 row-major [K,N] (ORIGINAL weight layout).
// In-kernel hi/lo bf16 split; 3 compensated passes: AhBh + AhBl + AlBh.
// CTA 128x128, 8 warps (64x32 each), K-chunk 32, reg-prefetch + dbl smem buffer.
// SMEM stage: Ahi[128][80B] Alo Bhi[32][272B] Blo = 37888 B; two stages.
#define A_PITCH 80
#define B_PITCH 272
#define A_TB    (128 * A_PITCH)        // 10240
#define B_TB    (32 * B_PITCH)         // 8704
#define STAGE_B (2 * A_TB + 2 * B_TB)  // 37888
#define HG_SMEM (2 * STAGE_B)          // 75776

__global__ void __launch_bounds__(256)
hgemm_kernel(const float* __restrict__ A,
             const float* __restrict__ B,
             const float* __restrict__ bias,
             const float* __restrict__ res,
             float* __restrict__ C, int M, int N, int K)
{
    extern __shared__ char sm[];
    const uint32_t smb = smem_u32(sm);

    const int tid  = threadIdx.x;
    const int wid  = tid >> 5, lane = tid & 31;
    const int wm   = wid >> 2;          // 0..1
    const int wn   = wid & 3;           // 0..3
    const int m0 = blockIdx.y * 128, n0 = blockIdx.x * 128;

    const int nc = K >> 5;

    // loader mapping
    const int arow = tid >> 1, aq = tid & 1;     // A: row 0..127, col base aq*16
    const int brow = tid >> 3, bq = tid & 7;     // B: row 0..31,  col base bq*16

    const float* Abase = A + (size_t)(m0 + arow) * K + aq * 16;
    const float* Bbase = B + (size_t)brow * N + n0 + bq * 16;

    float4 pf[8];
    auto ldg_chunk = [&](int c) {
        const float* a = Abase + c * 32;
        #pragma unroll
        for (int i = 0; i < 4; i++) pf[i] = *(const float4*)(a + 4 * i);
        const float* b = Bbase + (size_t)c * 32 * N;
        #pragma unroll
        for (int i = 0; i < 4; i++) pf[4 + i] = *(const float4*)(b + 4 * i);
    };
    auto cvt_sts = [&](int s) {
        const uint32_t st = smb + s * STAGE_B;
        #pragma unroll
        for (int i = 0; i < 4; i++) {
            uint32_t h0, l0, h1, l1;
            split2(pf[i].x, pf[i].y, h0, l0);
            split2(pf[i].z, pf[i].w, h1, l1);
            const uint32_t ad = st + arow * A_PITCH + (aq * 16 + 4 * i) * 2;
            sts8(ad,        h0, h1);
            sts8(ad + A_TB, l0, l1);
        }
        #pragma unroll
        for (int i = 0; i < 4; i++) {
            uint32_t h0, l0, h1, l1;
            split2(pf[4 + i].x, pf[4 + i].y, h0, l0);
            split2(pf[4 + i].z, pf[4 + i].w, h1, l1);
            const uint32_t ad = st + 2 * A_TB + brow * B_PITCH + (bq * 16 + 4 * i) * 2;
            sts8(ad,        h0, h1);
            sts8(ad + B_TB, l0, l1);
        }
    };

    float acc[4][4][4];
    #pragma unroll
    for (int a = 0; a < 4; a++)
        #pragma unroll
        for (int b = 0; b < 4; b++)
            #pragma unroll
            for (int r = 0; r < 4; r++) acc[a][b][r] = 0.f;

    ldg_chunk(0);
    cvt_sts(0);
    __syncthreads();

    for (int c = 0; c < nc; c++) {
        if (c + 1 < nc) ldg_chunk(c + 1);

        const uint32_t stage = smb + (c & 1) * STAGE_B;
        const uint32_t sAh = stage, sAl = stage + A_TB;
        const uint32_t sBh = stage + 2 * A_TB, sBl = sBh + B_TB;

        #pragma unroll
        for (int ks = 0; ks < 2; ks++) {
            uint32_t ah[4][4], al[4][4];
            const uint32_t acb = ks * 32 + ((lane >> 4) * 16);
            #pragma unroll
            for (int mt = 0; mt < 4; mt++) {
                const uint32_t ro = (wm * 64 + mt * 16 + (lane & 15)) * A_PITCH + acb;
                ldm_x4(ah[mt], sAh + ro);
                ldm_x4(al[mt], sAl + ro);
            }
            // B row for ldmatrix.trans: k row = ks*16 + (lane&15)
            const uint32_t brow16 = (ks * 16 + (lane & 15)) * B_PITCH;
            #pragma unroll
            for (int nt = 0; nt < 4; nt++) {
                const uint32_t co = (wn * 32 + nt * 8) * 2;
                uint32_t bh[2], bl[2];
                ldm_x2_trans(bh, sBh + brow16 + co);
                ldm_x2_trans(bl, sBl + brow16 + co);
                #pragma unroll
                for (int mt = 0; mt < 4; mt++) {
                    mma_bf16(acc[mt][nt], ah[mt], bh);
                    mma_bf16(acc[mt][nt], ah[mt], bl);
                    mma_bf16(acc[mt][nt], al[mt], bh);
                }
            }
        }

        if (c + 1 < nc) cvt_sts((c + 1) & 1);
        __syncthreads();
    }

    // epilogue (same mapping as R3)
    #pragma unroll
    for (int mt = 0; mt < 4; mt++) {
        #pragma unroll
        for (int nt = 0; nt < 4; nt++) {
            const int col = n0 + wn * 32 + nt * 8 + (lane & 3) * 2;
            float bv0 = 0.f, bv1 = 0.f;
            if (bias) { bv0 = bias[col]; bv1 = bias[col + 1]; }
            #pragma unroll
            for (int hh = 0; hh < 2; hh++) {
                const int row = m0 + wm * 64 + mt * 16 + (lane >> 2) + hh * 8;
                float v0 = acc[mt][nt][hh * 2]     + bv0;
                float v1 = acc[mt][nt][hh * 2 + 1] + bv1;
                const size_t off = (size_t)row * N + col;
                if (res) { v0 += res[off]; v1 += res[off + 1]; }
                C[off]     = v0;
                C[off + 1] = v1;
            }
        }
    }
}

// ======================= RMSNorm =============================================
__global__ void rmsnorm_kernel(const float* __restrict__ x,
                               const float* __restrict__ w,
                               float* __restrict__ out)
{
    const int row = blockIdx.x;
    const float* xr = x + (size_t)row * DMODEL;
    float s = 0.f;
    for (int i = threadIdx.x; i < DMODEL; i += 256) { float v = xr[i]; s += v * v; }
    #pragma unroll
    for (int off = 16; off; off >>= 1) s += __shfl_down_sync(0xffffffffu, s, off);
    __shared__ float red[8];
    const int warp = threadIdx.x >> 5, lane = threadIdx.x & 31;
    if (lane == 0) red[warp] = s;
    __syncthreads();
    if (warp == 0) {
        float t = (lane < 8) ? red[lane] : 0.f;
        #pragma unroll
        for (int off = 4; off; off >>= 1) t += __shfl_down_sync(0xffu, t, off);
        if (lane == 0) red[0] = t;
    }
    __syncthreads();
    const float inv = rsqrtf(red[0] * (1.0f / DMODEL) + 1e-5f);
    for (int i = threadIdx.x; i < DMODEL; i += 256)
        out[(size_t)row * DMODEL + i] = xr[i] * inv * w[i];
}

// ======================= RoPE ================================================
__global__ void rope_kernel(float* __restrict__ q, float* __restrict__ k,
                            const int* __restrict__ tok_id)
{
    const int idx = blockIdx.x * blockDim.x + threadIdx.x;
    if (idx >= SLEN * NH * 32) return;
    const int i = idx & 31;
    const int h = (idx >> 5) & 15;
    const int s = idx >> 9;
    const double inv = pow(10000.0, -(double)i / 32.0);
    const double ang = (double)tok_id[s] * inv;
    double sd, cd;
    sincos(ang, &sd, &cd);
    const float c = (float)cd, sn = (float)sd;
    const size_t base = (size_t)s * DMODEL + h * HDIM;
    float x1 = q[base + i], x2 = q[base + 32 + i];
    q[base + i]      = x1 * c - x2 * sn;
    q[base + 32 + i] = x1 * sn + x2 * c;
    float y1 = k[base + i], y2 = k[base + 32 + i];
    k[base + i]      = y1 * c - y2 * sn;
    k[base + 32 + i] = y1 * sn + y2 * c;
}

// ======================= local masked attention ==============================
__global__ void attn_kernel(const float* __restrict__ q,
                            const float* __restrict__ k,
                            const float* __restrict__ v,
                            const int* __restrict__ doc_id,
                            const int* __restrict__ tok_id,
                            float* __restrict__ o)
{
    const int s = blockIdx.x;
    const int h = blockIdx.y;
    const int tid = threadIdx.x;
    const int warp = tid >> 5, lane = tid & 31;

    __shared__ float qs[HDIM];
    __shared__ float sc[256];
    __shared__ float red[4];
    __shared__ float oacc[HDIM];

    if (tid < HDIM) qs[tid] = q[(size_t)s * DMODEL + h * HDIM + tid];
    __syncthreads();

    int kstart = s - 127; if (kstart < 0) kstart = 0;
    int kend   = s + 127; if (kend > SLEN - 1) kend = SLEN - 1;
    const int nk = kend - kstart + 1;
    const int myDoc = doc_id[s];
    const int myTok = tok_id[s];

    for (int j = warp; j < nk; j += 4) {
        const int kk = kstart + j;
        const size_t kb = (size_t)kk * DMODEL + h * HDIM;
        float p = qs[lane] * k[kb + lane] + qs[lane + 32] * k[kb + lane + 32];
        #pragma unroll
        for (int off = 16; off; off >>= 1) p += __shfl_down_sync(0xffffffffu, p, off);
        if (lane == 0) {
            const bool ok = (doc_id[kk] == myDoc) && (abs(tok_id[kk] - myTok) < 128);
            sc[j] = ok ? p * 0.125f : -1e30f;
        }
    }
    __syncthreads();

    float m = -1e30f;
    for (int j = tid; j < nk; j += 128) m = fmaxf(m, sc[j]);
    #pragma unroll
    for (int off = 16; off; off >>= 1) m = fmaxf(m, __shfl_down_sync(0xffffffffu, m, off));
    if (lane == 0) red[warp] = m;
    __syncthreads();
    m = fmaxf(fmaxf(red[0], red[1]), fmaxf(red[2], red[3]));
    __syncthreads();

    float sum = 0.f;
    for (int j = tid; j < nk; j += 128) {
        const float e = expf(sc[j] - m);
        sc[j] = e;
        sum += e;
    }
    #pragma unroll
    for (int off = 16; off; off >>= 1) sum += __shfl_down_sync(0xffffffffu, sum, off);
    if (lane == 0) red[warp] = sum;
    __syncthreads();
    sum = red[0] + red[1] + red[2] + red[3];
    const float inv = 1.0f / sum;
    __syncthreads();

    const int d = tid & 63;
    const int half = tid >> 6;
    float acc = 0.f;
    for (int j = half; j < nk; j += 2)
        acc += sc[j] * v[(size_t)(kstart + j) * DMODEL + h * HDIM + d];
    if (half == 1) oacc[d] = acc;
    __syncthreads();
    if (half == 0)
        o[(size_t)s * DMODEL + h * HDIM + d] = (acc + oacc[d]) * inv;
}

// ======================= SiLU gate ===========================================
__global__ void silu_kernel(float* __restrict__ f1, const float* __restrict__ f3)
{
    const int idx = blockIdx.x * blockDim.x + threadIdx.x;
    const float a = f1[idx];
    f1[idx] = (a / (1.0f + expf(-a))) * f3[idx];
}

// ======================= launch ==============================================
static void run_gemm(const float* A, const float* B, const float* bias,
                     const float* res, float* C, int M, int N, int K)
{
    dim3 g(N / 128, M / 128);
    hgemm_kernel<<<g, 256, HG_SMEM>>>(A, B, bias, res, C, M, N, K);
}

extern "C" void kernel_launch(void* const* d_in, const int* in_sizes, int n_in,
                              void* d_out, int out_size)
{
    const float* x           = (const float*)d_in[0];
    const float* emb_w       = (const float*)d_in[1];
    const float* emb_b       = (const float*)d_in[2];
    const float* wq          = (const float*)d_in[3];
    const float* wk          = (const float*)d_in[4];
    const float* wv          = (const float*)d_in[5];
    const float* wo          = (const float*)d_in[6];
    const float* attn_norm_w = (const float*)d_in[7];
    const float* ffn_norm_w  = (const float*)d_in[8];
    const float* w1          = (const float*)d_in[9];
    const float* w2          = (const float*)d_in[10];
    const float* w3          = (const float*)d_in[11];
    const float* out_norm_w  = (const float*)d_in[12];
    const float* out_w       = (const float*)d_in[13];
    const int*   doc_id      = (const int*)d_in[14];
    const int*   tok_id      = (const int*)d_in[15];
    float* out = (float*)d_out;

    cudaFuncSetAttribute(hgemm_kernel,
                         cudaFuncAttributeMaxDynamicSharedMemorySize, HG_SMEM);

    float *h, *hn, *q, *k, *v, *o, *f1, *f3;
    cudaGetSymbolAddress((void**)&h,  g_h);
    cudaGetSymbolAddress((void**)&hn, g_hn);
    cudaGetSymbolAddress((void**)&q,  g_q);
    cudaGetSymbolAddress((void**)&k,  g_k);
    cudaGetSymbolAddress((void**)&v,  g_v);
    cudaGetSymbolAddress((void**)&o,  g_o);
    cudaGetSymbolAddress((void**)&f1, g_f1);
    cudaGetSymbolAddress((void**)&f3, g_f3);

    // launch 0: embedding  h = x @ emb_w + emb_b
    run_gemm(x, emb_w, emb_b, nullptr, h, SLEN, DMODEL, IND);

    for (int l = 0; l < NLAYER; l++) {
        const size_t wqo = (size_t)l * DMODEL * (NH * HDIM);
        const size_t wfo = (size_t)l * DMODEL * FFND;
        const size_t w2o = (size_t)l * FFND * DMODEL;

        rmsnorm_kernel<<<SLEN, 256>>>(h, attn_norm_w + (size_t)l * DMODEL, hn);
        run_gemm(hn, wq + wqo, nullptr, nullptr, q, SLEN, DMODEL, DMODEL);
        run_gemm(hn, wk + wqo, nullptr, nullptr, k, SLEN, DMODEL, DMODEL);
        rope_kernel<<<(SLEN * NH * 32 + 255) / 256, 256>>>(q, k, tok_id);
        run_gemm(hn, wv + wqo, nullptr, nullptr, v, SLEN, DMODEL, DMODEL);  // launch idx 5 on l==0
        attn_kernel<<<dim3(SLEN, NH), 128>>>(q, k, v, doc_id, tok_id, o);
        run_gemm(o, wo + wqo, nullptr, h, h, SLEN, DMODEL, DMODEL);

        rmsnorm_kernel<<<SLEN, 256>>>(h, ffn_norm_w + (size_t)l * DMODEL, hn);
        run_gemm(hn, w1 + wfo, nullptr, nullptr, f1, SLEN, FFND, DMODEL);
        run_gemm(hn, w3 + wfo, nullptr, nullptr, f3, SLEN, FFND, DMODEL);
        silu_kernel<<<(SLEN * FFND) / 256, 256>>>(f1, f3);
        run_gemm(f1, w2 + w2o, nullptr, h, h, SLEN, DMODEL, FFND);
    }

    rmsnorm_kernel<<<SLEN, 256>>>(h, out_norm_w, hn);
    run_gemm(hn, out_w, nullptr, nullptr, out, SLEN, OUTD, DMODEL);
}

// round 6
// speedup vs baseline: 1.1657x; 1.1657x over previous
#include <cuda_runtime.h>
#include <cuda_bf16.h>
#include <math.h>
#include <stdint.h>

#define SLEN   2048
#define DMODEL 1024
#define NH     16
#define HDIM   64
#define NLAYER 4
#define FFND   4096
#define OUTD   128
#define IND    64

// ======================= helpers =============================================
__device__ __forceinline__ uint32_t smem_u32(const void* p) {
    uint32_t a;
    asm("{ .reg .u64 t; cvta.to.shared.u64 t, %1; cvt.u32.u64 %0, t; }"
        : "=r"(a) : "l"(p));
    return a;
}
__device__ __forceinline__ void cp_async16(uint32_t dst, const void* src) {
    asm volatile("cp.async.cg.shared.global [%0], [%1], 16;" :: "r"(dst), "l"(src));
}
__device__ __forceinline__ void cp_commit() {
    asm volatile("cp.async.commit_group;" ::: "memory");
}
template <int NN> __device__ __forceinline__ void cp_wait() {
    asm volatile("cp.async.wait_group %0;" :: "n"(NN) : "memory");
}
__device__ __forceinline__ void ldm_x4(uint32_t* r, uint32_t addr) {
    asm volatile("ldmatrix.sync.aligned.m8n8.x4.shared.b16 {%0,%1,%2,%3}, [%4];"
                 : "=r"(r[0]), "=r"(r[1]), "=r"(r[2]), "=r"(r[3]) : "r"(addr));
}
__device__ __forceinline__ void ldm_x2_trans(uint32_t* r, uint32_t addr) {
    asm volatile("ldmatrix.sync.aligned.m8n8.x2.trans.shared.b16 {%0,%1}, [%2];"
                 : "=r"(r[0]), "=r"(r[1]) : "r"(addr));
}
__device__ __forceinline__ void mma_bf16(float* c, const uint32_t* a, const uint32_t* b) {
    asm volatile(
        "mma.sync.aligned.m16n8k16.row.col.f32.bf16.bf16.f32 "
        "{%0,%1,%2,%3}, {%4,%5,%6,%7}, {%8,%9}, {%0,%1,%2,%3};"
        : "+f"(c[0]), "+f"(c[1]), "+f"(c[2]), "+f"(c[3])
        : "r"(a[0]), "r"(a[1]), "r"(a[2]), "r"(a[3]), "r"(b[0]), "r"(b[1]));
}
__device__ __forceinline__ void sts8(uint32_t addr, uint32_t a, uint32_t b) {
    asm volatile("st.shared.v2.b32 [%0], {%1,%2};" :: "r"(addr), "r"(a), "r"(b));
}
__device__ __forceinline__ void split2(float x, float y, uint32_t& h, uint32_t& l) {
    __nv_bfloat16 hx = __float2bfloat16(x), hy = __float2bfloat16(y);
    __nv_bfloat16 lx = __float2bfloat16(x - __bfloat162float(hx));
    __nv_bfloat16 ly = __float2bfloat16(y - __bfloat162float(hy));
    __nv_bfloat162 hp = __halves2bfloat162(hx, hy);
    __nv_bfloat162 lp = __halves2bfloat162(lx, ly);
    h = *reinterpret_cast<uint32_t*>(&hp);
    l = *reinterpret_cast<uint32_t*>(&lp);
}

// ======================= scratch =============================================
// pre-split weights (same [K,N] layout, fused column groups):
//  emb [64,1024] @0 ; per layer l @65536+l*16M:
//    qkv [1024,3072] @+0 ; wo [1024,1024] @+3M ; w13 [1024,8192] @+4M ;
//    w2 [4096,1024] @+12M ;  out [1024,128] @ 65536+64M
#define LSTR    16777216u
#define OFF_L   65536u
#define OFF_OUT (65536u + 4u * LSTR)
#define WTOT    (OFF_OUT + 131072u)
__device__ __nv_bfloat16 g_whi[WTOT];
__device__ __nv_bfloat16 g_wlo[WTOT];

__device__ float g_h  [SLEN * DMODEL];
__device__ float g_hn [SLEN * DMODEL];
__device__ float g_qkv[SLEN * 3 * DMODEL];
__device__ float g_o  [SLEN * DMODEL];
__device__ float g_f13[SLEN * 2 * FFND];

// ============ weight hi/lo split (elementwise, layout-preserving) ============
__global__ void wsplit_kernel(const float* __restrict__ W,
                              __nv_bfloat16* __restrict__ hi,
                              __nv_bfloat16* __restrict__ lo,
                              int Nsrc, int P, int c0, int total4)
{
    const int i = blockIdx.x * blockDim.x + threadIdx.x;
    if (i >= total4) return;
    const int e = i * 4;
    const int k = e / Nsrc, n = e % Nsrc;
    const float4 v = *(const float4*)(W + e);
    uint32_t h0, l0, h1, l1;
    split2(v.x, v.y, h0, l0);
    split2(v.z, v.w, h1, l1);
    const size_t d = (size_t)k * P + c0 + n;
    *(uint32_t*)(hi + d)     = h0;
    *(uint32_t*)(hi + d + 2) = h1;
    *(uint32_t*)(lo + d)     = l0;
    *(uint32_t*)(lo + d + 2) = l1;
}

// ============ HMMA GEMM: C[M,N] = A[M,K] @ B[K,N] (+bias)(+res) ==============
// A fp32 [M,Ap] (in-kernel hi/lo split), B pre-split bf16 hi/lo [K,N].
// 3 compensated passes: AhBh + AhBl + AlBh. CTA 128x128, 8 warps, K-chunk 32.
#define A_PITCH 80
#define B_PITCH 272
#define A_TB    (128 * A_PITCH)        // 10240
#define B_TB    (32 * B_PITCH)         // 8704
#define STAGE_B (2 * A_TB + 2 * B_TB)  // 37888
#define HG_SMEM (2 * STAGE_B)

__global__ void __launch_bounds__(256)
hgemm_kernel(const float* __restrict__ A,
             const __nv_bfloat16* __restrict__ Bhi,
             const __nv_bfloat16* __restrict__ Blo,
             const float* __restrict__ bias,
             const float* __restrict__ res,
             float* __restrict__ C, int M, int N, int K, int Ap)
{
    extern __shared__ char sm[];
    const uint32_t smb = smem_u32(sm);

    const int tid  = threadIdx.x;
    const int wid  = tid >> 5, lane = tid & 31;
    const int wm   = wid >> 2;
    const int wn   = wid & 3;
    const int m0 = blockIdx.y * 128, n0 = blockIdx.x * 128;
    const int nc = K >> 5;

    const int arow = tid >> 1, aq = tid & 1;
    const float* Abase = A + (size_t)(m0 + arow) * Ap + aq * 16;

    float4 pf[4];
    auto ldgA = [&](int c) {
        const float* a = Abase + c * 32;
        #pragma unroll
        for (int i = 0; i < 4; i++) pf[i] = *(const float4*)(a + 4 * i);
    };
    auto stsA = [&](int s) {
        const uint32_t st = smb + s * STAGE_B;
        #pragma unroll
        for (int i = 0; i < 4; i++) {
            uint32_t h0, l0, h1, l1;
            split2(pf[i].x, pf[i].y, h0, l0);
            split2(pf[i].z, pf[i].w, h1, l1);
            const uint32_t ad = st + arow * A_PITCH + (aq * 16 + 4 * i) * 2;
            sts8(ad,        h0, h1);
            sts8(ad + A_TB, l0, l1);
        }
    };
    auto cpB = [&](int c, int s) {
        const uint32_t st = smb + s * STAGE_B + 2 * A_TB;
        #pragma unroll
        for (int i = 0; i < 4; i++) {
            const int idx  = tid + i * 256;
            const int tile = idx >> 9;
            const int r    = (idx >> 4) & 31;
            const int g    = idx & 15;
            const __nv_bfloat16* src =
                (tile ? Blo : Bhi) + (size_t)(c * 32 + r) * N + n0 + g * 8;
            cp_async16(st + tile * B_TB + r * B_PITCH + g * 16, src);
        }
        cp_commit();
    };

    float acc[4][4][4];
    #pragma unroll
    for (int a = 0; a < 4; a++)
        #pragma unroll
        for (int b = 0; b < 4; b++)
            #pragma unroll
            for (int r = 0; r < 4; r++) acc[a][b][r] = 0.f;

    ldgA(0);
    cpB(0, 0);
    stsA(0);
    cp_wait<0>();
    __syncthreads();

    for (int c = 0; c < nc; c++) {
        if (c + 1 < nc) { ldgA(c + 1); cpB(c + 1, (c + 1) & 1); }

        const uint32_t stage = smb + (c & 1) * STAGE_B;
        const uint32_t sAh = stage, sAl = stage + A_TB;
        const uint32_t sBh = stage + 2 * A_TB, sBl = sBh + B_TB;

        #pragma unroll
        for (int ks = 0; ks < 2; ks++) {
            uint32_t ah[4][4], al[4][4];
            const uint32_t acb = ks * 32 + ((lane >> 4) * 16);
            #pragma unroll
            for (int mt = 0; mt < 4; mt++) {
                const uint32_t ro = (wm * 64 + mt * 16 + (lane & 15)) * A_PITCH + acb;
                ldm_x4(ah[mt], sAh + ro);
                ldm_x4(al[mt], sAl + ro);
            }
            const uint32_t brow16 = (ks * 16 + (lane & 15)) * B_PITCH;
            #pragma unroll
            for (int nt = 0; nt < 4; nt++) {
                const uint32_t co = (wn * 32 + nt * 8) * 2;
                uint32_t bh[2], bl[2];
                ldm_x2_trans(bh, sBh + brow16 + co);
                ldm_x2_trans(bl, sBl + brow16 + co);
                #pragma unroll
                for (int mt = 0; mt < 4; mt++) {
                    mma_bf16(acc[mt][nt], ah[mt], bh);
                    mma_bf16(acc[mt][nt], ah[mt], bl);
                    mma_bf16(acc[mt][nt], al[mt], bh);
                }
            }
        }

        if (c + 1 < nc) stsA((c + 1) & 1);
        cp_wait<0>();
        __syncthreads();
    }

    #pragma unroll
    for (int mt = 0; mt < 4; mt++) {
        #pragma unroll
        for (int nt = 0; nt < 4; nt++) {
            const int col = n0 + wn * 32 + nt * 8 + (lane & 3) * 2;
            float bv0 = 0.f, bv1 = 0.f;
            if (bias) { bv0 = bias[col]; bv1 = bias[col + 1]; }
            #pragma unroll
            for (int hh = 0; hh < 2; hh++) {
                const int row = m0 + wm * 64 + mt * 16 + (lane >> 2) + hh * 8;
                float v0 = acc[mt][nt][hh * 2]     + bv0;
                float v1 = acc[mt][nt][hh * 2 + 1] + bv1;
                const size_t off = (size_t)row * N + col;
                if (res) { v0 += res[off]; v1 += res[off + 1]; }
                C[off]     = v0;
                C[off + 1] = v1;
            }
        }
    }
}

// ======================= RMSNorm =============================================
__global__ void rmsnorm_kernel(const float* __restrict__ x,
                               const float* __restrict__ w,
                               float* __restrict__ out)
{
    const int row = blockIdx.x;
    const float* xr = x + (size_t)row * DMODEL;
    float s = 0.f;
    for (int i = threadIdx.x; i < DMODEL; i += 256) { float v = xr[i]; s += v * v; }
    #pragma unroll
    for (int off = 16; off; off >>= 1) s += __shfl_down_sync(0xffffffffu, s, off);
    __shared__ float red[8];
    const int warp = threadIdx.x >> 5, lane = threadIdx.x & 31;
    if (lane == 0) red[warp] = s;
    __syncthreads();
    if (warp == 0) {
        float t = (lane < 8) ? red[lane] : 0.f;
        #pragma unroll
        for (int off = 4; off; off >>= 1) t += __shfl_down_sync(0xffu, t, off);
        if (lane == 0) red[0] = t;
    }
    __syncthreads();
    const float inv = rsqrtf(red[0] * (1.0f / DMODEL) + 1e-5f);
    for (int i = threadIdx.x; i < DMODEL; i += 256)
        out[(size_t)row * DMODEL + i] = xr[i] * inv * w[i];
}

// ======================= RoPE (on fused qkv buffer) ==========================
__global__ void rope_kernel(float* __restrict__ qkv, const int* __restrict__ tok_id)
{
    const int idx = blockIdx.x * blockDim.x + threadIdx.x;
    if (idx >= SLEN * NH * 32) return;
    const int i = idx & 31;
    const int h = (idx >> 5) & 15;
    const int s = idx >> 9;
    const double inv = pow(10000.0, -(double)i / 32.0);
    const double ang = (double)tok_id[s] * inv;
    double sd, cd;
    sincos(ang, &sd, &cd);
    const float c = (float)cd, sn = (float)sd;
    const size_t qb = (size_t)s * 3072 + h * HDIM;
    const size_t kb = qb + 1024;
    float x1 = qkv[qb + i], x2 = qkv[qb + 32 + i];
    qkv[qb + i]      = x1 * c - x2 * sn;
    qkv[qb + 32 + i] = x1 * sn + x2 * c;
    float y1 = qkv[kb + i], y2 = qkv[kb + 32 + i];
    qkv[kb + i]      = y1 * c - y2 * sn;
    qkv[kb + 32 + i] = y1 * sn + y2 * c;
}

// ======================= tiled local attention ===============================
// Block = (64-query tile, head). Window [q0-128, q0+192) = 5 chunks of 64.
// Online softmax; Q,K,V,S tiles in dynamic SMEM (pad 65 rows).
#define AT_PAD   65
#define AT_TILE  (64 * AT_PAD)
#define ATTN_SMEM (4 * AT_TILE * 4)

__global__ void __launch_bounds__(256)
attn_kernel(const float* __restrict__ qkv,
            const int* __restrict__ doc_id,
            const int* __restrict__ tok_id,
            float* __restrict__ o)
{
    extern __shared__ float as_[];
    float* Qs = as_;
    float* Ks = Qs + AT_TILE;
    float* Vs = Ks + AT_TILE;
    float* Sc = Vs + AT_TILE;

    const int q0 = blockIdx.x * 64;
    const int h  = blockIdx.y;
    const int tid = threadIdx.x;
    const int q = tid >> 2, quad = tid & 3;

    // load Q tile
    #pragma unroll
    for (int j = 0; j < 16; j++) {
        const int e = tid + j * 256;
        const int r = e >> 6, cl = e & 63;
        Qs[r * AT_PAD + cl] = qkv[(size_t)(q0 + r) * 3072 + h * HDIM + cl];
    }

    const int myS = q0 + q;
    const int myDoc = doc_id[myS], myTok = tok_id[myS];

    float m = -1e29f, l = 0.f, O[16];
    #pragma unroll
    for (int j = 0; j < 16; j++) O[j] = 0.f;

    // per-thread Q fragment for partial dots
    float qr[16];
    __syncthreads();
    #pragma unroll
    for (int j = 0; j < 16; j++) qr[j] = Qs[q * AT_PAD + quad * 16 + j];

    const int kbase0 = q0 - 128;
    for (int ch = 0; ch < 5; ch++) {
        const int kb = kbase0 + ch * 64;
        __syncthreads();
        // load K,V chunk (zero OOB)
        #pragma unroll
        for (int j = 0; j < 16; j++) {
            const int e = tid + j * 256;
            const int r = e >> 6, cl = e & 63;
            const int kg = kb + r;
            const bool in = (kg >= 0) & (kg < SLEN);
            const size_t kbase = (size_t)(in ? kg : 0) * 3072 + h * HDIM + cl;
            Ks[r * AT_PAD + cl] = in ? qkv[kbase + 1024] : 0.f;
            Vs[r * AT_PAD + cl] = in ? qkv[kbase + 2048] : 0.f;
        }
        __syncthreads();

        // scores: partial dot over this thread's 16 dims, quad-reduce
        #pragma unroll 4
        for (int kk = 0; kk < 16; kk++) {
            const int k = quad + kk * 4;
            float p = 0.f;
            #pragma unroll
            for (int j = 0; j < 16; j++)
                p += qr[j] * Ks[k * AT_PAD + quad * 16 + j];
            // wait: each thread's partial uses ITS quad dims but k=quad+..; need
            // full dot: reduce partials of the 4 quads for same (q,k). The 4
            // threads of a quad have DIFFERENT k here, so restructure below.
            Sc[q * AT_PAD + k] = p;  // placeholder, fixed below
        }
        __syncthreads();
        // fix-up: accumulate remaining 48 dims per (q,k) cooperatively:
        // thread (q,quad) handles k = quad+kk*4, sums other quads' dims directly
        #pragma unroll 4
        for (int kk = 0; kk < 16; kk++) {
            const int k = quad + kk * 4;
            float p = Sc[q * AT_PAD + k];
            #pragma unroll
            for (int qd = 0; qd < 4; qd++) {
                if (qd == quad) continue;
                #pragma unroll
                for (int j = 0; j < 16; j++)
                    p += Qs[q * AT_PAD + qd * 16 + j] * Ks[k * AT_PAD + qd * 16 + j];
            }
            const int kg = kb + k;
            bool ok = (kg >= 0) && (kg < SLEN);
            if (ok) ok = (doc_id[kg] == myDoc) && (abs(tok_id[kg] - myTok) < 128);
            Sc[q * AT_PAD + k] = ok ? p * 0.125f : -1e30f;
        }
        __syncthreads();

        // online softmax + PV for this thread's (q, dims quad*16..)
        float cm = -1e30f;
        #pragma unroll 8
        for (int k = 0; k < 64; k++) cm = fmaxf(cm, Sc[q * AT_PAD + k]);
        const float mn = fmaxf(m, cm);
        const float scale = __expf(m - mn);
        l *= scale;
        #pragma unroll
        for (int j = 0; j < 16; j++) O[j] *= scale;
        #pragma unroll 4
        for (int k = 0; k < 64; k++) {
            const float p = __expf(Sc[q * AT_PAD + k] - mn);
            l += p;
            #pragma unroll
            for (int j = 0; j < 16; j++)
                O[j] += p * Vs[k * AT_PAD + quad * 16 + j];
        }
        m = mn;
    }

    const float inv = 1.0f / l;
    #pragma unroll
    for (int j = 0; j < 16; j++)
        o[(size_t)myS * DMODEL + h * HDIM + quad * 16 + j] = O[j] * inv;
}

// ======================= SiLU gate (in-place on fused f13) ===================
__global__ void silu_kernel(float* __restrict__ f13)
{
    const int idx = blockIdx.x * blockDim.x + threadIdx.x;
    const int r = idx >> 12, n = idx & 4095;
    const size_t b = (size_t)r * 8192 + n;
    const float a = f13[b];
    f13[b] = (a / (1.0f + __expf(-a))) * f13[b + 4096];
}

// ======================= launch ==============================================
static void run_gemm(const float* A, const __nv_bfloat16* Bhi, const __nv_bfloat16* Blo,
                     const float* bias, const float* res, float* C,
                     int M, int N, int K, int Ap)
{
    dim3 g(N / 128, M / 128);
    hgemm_kernel<<<g, 256, HG_SMEM>>>(A, Bhi, Blo, bias, res, C, M, N, K, Ap);
}

static void run_split(const float* W, __nv_bfloat16* hi, __nv_bfloat16* lo,
                      int K, int Nsrc, int P, int c0)
{
    const int t4 = K * Nsrc / 4;
    wsplit_kernel<<<(t4 + 255) / 256, 256>>>(W, hi, lo, Nsrc, P, c0, t4);
}

extern "C" void kernel_launch(void* const* d_in, const int* in_sizes, int n_in,
                              void* d_out, int out_size)
{
    const float* x           = (const float*)d_in[0];
    const float* emb_w       = (const float*)d_in[1];
    const float* emb_b       = (const float*)d_in[2];
    const float* wq          = (const float*)d_in[3];
    const float* wk          = (const float*)d_in[4];
    const float* wv          = (const float*)d_in[5];
    const float* wo          = (const float*)d_in[6];
    const float* attn_norm_w = (const float*)d_in[7];
    const float* ffn_norm_w  = (const float*)d_in[8];
    const float* w1          = (const float*)d_in[9];
    const float* w2          = (const float*)d_in[10];
    const float* w3          = (const float*)d_in[11];
    const float* out_norm_w  = (const float*)d_in[12];
    const float* out_w       = (const float*)d_in[13];
    const int*   doc_id      = (const int*)d_in[14];
    const int*   tok_id      = (const int*)d_in[15];
    float* out = (float*)d_out;

    cudaFuncSetAttribute(hgemm_kernel,
                         cudaFuncAttributeMaxDynamicSharedMemorySize, HG_SMEM);
    cudaFuncSetAttribute(attn_kernel,
                         cudaFuncAttributeMaxDynamicSharedMemorySize, ATTN_SMEM);

    float *h, *hn, *qkv, *o, *f13;
    __nv_bfloat16 *whi, *wlo;
    cudaGetSymbolAddress((void**)&h,   g_h);
    cudaGetSymbolAddress((void**)&hn,  g_hn);
    cudaGetSymbolAddress((void**)&qkv, g_qkv);
    cudaGetSymbolAddress((void**)&o,   g_o);
    cudaGetSymbolAddress((void**)&f13, g_f13);
    cudaGetSymbolAddress((void**)&whi, g_whi);
    cudaGetSymbolAddress((void**)&wlo, g_wlo);

    // ---- one-time weight split into fused layouts ----
    run_split(emb_w, whi, wlo, IND, DMODEL, DMODEL, 0);
    for (int l = 0; l < NLAYER; l++) {
        __nv_bfloat16* hb = whi + OFF_L + (size_t)l * LSTR;
        __nv_bfloat16* lb = wlo + OFF_L + (size_t)l * LSTR;
        const size_t wqo = (size_t)l * DMODEL * DMODEL;
        const size_t wfo = (size_t)l * DMODEL * FFND;
        run_split(wq + wqo, hb, lb, DMODEL, DMODEL, 3072, 0);
        run_split(wk + wqo, hb, lb, DMODEL, DMODEL, 3072, 1024);
        run_split(wv + wqo, hb, lb, DMODEL, DMODEL, 3072, 2048);
        run_split(wo + wqo, hb + 3145728, lb + 3145728, DMODEL, DMODEL, 1024, 0);
        run_split(w1 + wfo, hb + 4194304, lb + 4194304, DMODEL, FFND, 8192, 0);
        run_split(w3 + wfo, hb + 4194304, lb + 4194304, DMODEL, FFND, 8192, 4096);
        run_split(w2 + wfo, hb + 12582912, lb + 12582912, FFND, DMODEL, 1024, 0);
    }
    run_split(out_w, whi + OFF_OUT, wlo + OFF_OUT, DMODEL, OUTD, OUTD, 0);

    // ---- embedding ----
    run_gemm(x, whi, wlo, emb_b, nullptr, h, SLEN, DMODEL, IND, IND);

    for (int l = 0; l < NLAYER; l++) {
        const __nv_bfloat16* hb = whi + OFF_L + (size_t)l * LSTR;
        const __nv_bfloat16* lb = wlo + OFF_L + (size_t)l * LSTR;

        rmsnorm_kernel<<<SLEN, 256>>>(h, attn_norm_w + (size_t)l * DMODEL, hn);
        run_gemm(hn, hb, lb, nullptr, nullptr, qkv, SLEN, 3072, DMODEL, DMODEL);
        rope_kernel<<<(SLEN * NH * 32 + 255) / 256, 256>>>(qkv, tok_id);
        attn_kernel<<<dim3(SLEN / 64, NH), 256, ATTN_SMEM>>>(qkv, doc_id, tok_id, o);
        run_gemm(o, hb + 3145728, lb + 3145728, nullptr, h, h,
                 SLEN, DMODEL, DMODEL, DMODEL);

        rmsnorm_kernel<<<SLEN, 256>>>(h, ffn_norm_w + (size_t)l * DMODEL, hn);
        run_gemm(hn, hb + 4194304, lb + 4194304, nullptr, nullptr, f13,
                 SLEN, 2 * FFND, DMODEL, DMODEL);
        silu_kernel<<<(SLEN * FFND) / 256, 256>>>(f13);
        run_gemm(f13, hb + 12582912, lb + 12582912, nullptr, h, h,
                 SLEN, DMODEL, FFND, 2 * FFND);
    }

    rmsnorm_kernel<<<SLEN, 256>>>(h, out_norm_w, hn);
    run_gemm(hn, whi + OFF_OUT, wlo + OFF_OUT, nullptr, nullptr, out,
             SLEN, OUTD, DMODEL, DMODEL);
}

// round 9
// speedup vs baseline: 1.3443x; 1.1533x over previous
#include <cuda_runtime.h>
#include <cuda_bf16.h>
#include <math.h>
#include <stdint.h>

#define SLEN   2048
#define DMODEL 1024
#define NH     16
#define HDIM   64
#define NLAYER 4
#define FFND   4096
#define OUTD   128
#define IND    64

// ======================= helpers =============================================
__device__ __forceinline__ uint32_t smem_u32(const void* p) {
    uint32_t a;
    asm("{ .reg .u64 t; cvta.to.shared.u64 t, %1; cvt.u32.u64 %0, t; }"
        : "=r"(a) : "l"(p));
    return a;
}
__device__ __forceinline__ void cp_async16(uint32_t dst, const void* src) {
    asm volatile("cp.async.cg.shared.global [%0], [%1], 16;" :: "r"(dst), "l"(src));
}
__device__ __forceinline__ void cp_commit() {
    asm volatile("cp.async.commit_group;" ::: "memory");
}
template <int NN> __device__ __forceinline__ void cp_wait() {
    asm volatile("cp.async.wait_group %0;" :: "n"(NN) : "memory");
}
__device__ __forceinline__ void ldm_x4(uint32_t* r, uint32_t addr) {
    asm volatile("ldmatrix.sync.aligned.m8n8.x4.shared.b16 {%0,%1,%2,%3}, [%4];"
                 : "=r"(r[0]), "=r"(r[1]), "=r"(r[2]), "=r"(r[3]) : "r"(addr));
}
__device__ __forceinline__ void ldm_x2_trans(uint32_t* r, uint32_t addr) {
    asm volatile("ldmatrix.sync.aligned.m8n8.x2.trans.shared.b16 {%0,%1}, [%2];"
                 : "=r"(r[0]), "=r"(r[1]) : "r"(addr));
}
__device__ __forceinline__ void mma_bf16(float* c, const uint32_t* a, const uint32_t* b) {
    asm volatile(
        "mma.sync.aligned.m16n8k16.row.col.f32.bf16.bf16.f32 "
        "{%0,%1,%2,%3}, {%4,%5,%6,%7}, {%8,%9}, {%0,%1,%2,%3};"
        : "+f"(c[0]), "+f"(c[1]), "+f"(c[2]), "+f"(c[3])
        : "r"(a[0]), "r"(a[1]), "r"(a[2]), "r"(a[3]), "r"(b[0]), "r"(b[1]));
}
__device__ __forceinline__ void sts8(uint32_t addr, uint32_t a, uint32_t b) {
    asm volatile("st.shared.v2.b32 [%0], {%1,%2};" :: "r"(addr), "r"(a), "r"(b));
}
__device__ __forceinline__ void split2(float x, float y, uint32_t& h, uint32_t& l) {
    __nv_bfloat16 hx = __float2bfloat16(x), hy = __float2bfloat16(y);
    __nv_bfloat16 lx = __float2bfloat16(x - __bfloat162float(hx));
    __nv_bfloat16 ly = __float2bfloat16(y - __bfloat162float(hy));
    __nv_bfloat162 hp = __halves2bfloat162(hx, hy);
    __nv_bfloat162 lp = __halves2bfloat162(lx, ly);
    h = *reinterpret_cast<uint32_t*>(&hp);
    l = *reinterpret_cast<uint32_t*>(&lp);
}

// ======================= scratch =============================================
// weights (bf16 hi/lo, [K,N] layout, fused column groups):
//  emb [64,1024] @0 ; per layer l @65536+l*16M:
//    qkv [1024,3072] @+0 ; wo [1024,1024] @+3M ;
//    w13 [1024,8192] @+4M (w1/w3 interleaved in 8-col groups) ; w2 [4096,1024] @+12M
//  out [1024,128] @ 65536+64M
#define LSTR    16777216u
#define OFF_L   65536u
#define OFF_OUT (65536u + 4u * LSTR)
#define WTOT    (OFF_OUT + 131072u)
__device__ __nv_bfloat16 g_whi[WTOT];
__device__ __nv_bfloat16 g_wlo[WTOT];

__device__ float g_h  [SLEN * DMODEL];
__device__ float g_hn [SLEN * DMODEL];
__device__ float g_qkv[SLEN * 3 * DMODEL];
__device__ float g_o  [SLEN * DMODEL];
__device__ float g_f  [SLEN * FFND];
__device__ float g_ct [SLEN * 32];
__device__ float g_st [SLEN * 32];

// ======================= trig table (once) ===================================
__global__ void trig_kernel(const int* __restrict__ tok_id,
                            float* __restrict__ ct, float* __restrict__ st)
{
    const int idx = blockIdx.x * blockDim.x + threadIdx.x;
    if (idx >= SLEN * 32) return;
    const int i = idx & 31, s = idx >> 5;
    const double inv = pow(10000.0, -(double)i / 32.0);
    const double ang = (double)tok_id[s] * inv;
    double sd, cd;
    sincos(ang, &sd, &cd);
    ct[idx] = (float)cd;
    st[idx] = (float)sd;
}

// ======================= batched weight split ================================
struct WSeg {
    const float* W;
    unsigned dstoff;
    int Nsrc, P, c0, grp, t4, blk0;
};
struct WTab { WSeg s[15]; int nseg; };

__global__ void __launch_bounds__(256)
wsplit_all(WTab t, __nv_bfloat16* __restrict__ hi, __nv_bfloat16* __restrict__ lo)
{
    const int b = blockIdx.x;
    int si = 0;
    #pragma unroll 1
    for (int j = 1; j < t.nseg; j++) if (b >= t.s[j].blk0) si = j;
    const WSeg sg = t.s[si];
    const int i = (b - sg.blk0) * 256 + threadIdx.x;
    if (i >= sg.t4) return;
    const int e = i * 4;
    const int k = e / sg.Nsrc, n = e - k * sg.Nsrc;
    const float4 v = *(const float4*)(sg.W + e);
    uint32_t h0, l0, h1, l1;
    split2(v.x, v.y, h0, l0);
    split2(v.z, v.w, h1, l1);
    const int col = sg.grp ? (((n >> 3) << 4) + (n & 7) + sg.c0) : (sg.c0 + n);
    const size_t d = sg.dstoff + (size_t)k * sg.P + col;
    *(uint32_t*)(hi + d)     = h0;
    *(uint32_t*)(hi + d + 2) = h1;
    *(uint32_t*)(lo + d)     = l0;
    *(uint32_t*)(lo + d + 2) = l1;
}

// ============ HMMA GEMM: C[M,N] = A[M,K] @ B[K,N] (+bias)(+res)(silu) ========
#define A_PITCH 80
#define B_PITCH 272
#define A_TB    (128 * A_PITCH)
#define B_TB    (32 * B_PITCH)
#define STAGE_B (2 * A_TB + 2 * B_TB)
#define HG_SMEM (2 * STAGE_B)

__global__ void __launch_bounds__(256)
hgemm_kernel(const float* __restrict__ A,
             const __nv_bfloat16* __restrict__ Bhi,
             const __nv_bfloat16* __restrict__ Blo,
             const float* __restrict__ bias,
             const float* __restrict__ res,
             float* __restrict__ C, int M, int N, int K, int Ap, int silu_mode)
{
    extern __shared__ char sm[];
    const uint32_t smb = smem_u32(sm);

    const int tid  = threadIdx.x;
    const int wid  = tid >> 5, lane = tid & 31;
    const int wm   = wid >> 2;
    const int wn   = wid & 3;
    const int m0 = blockIdx.y * 128, n0 = blockIdx.x * 128;
    const int nc = K >> 5;

    const int arow = tid >> 1, aq = tid & 1;
    const float* Abase = A + (size_t)(m0 + arow) * Ap + aq * 16;

    float4 pf[4];
    auto ldgA = [&](int c) {
        const float* a = Abase + c * 32;
        #pragma unroll
        for (int i = 0; i < 4; i++) pf[i] = *(const float4*)(a + 4 * i);
    };
    auto stsA = [&](int s) {
        const uint32_t st = smb + s * STAGE_B;
        #pragma unroll
        for (int i = 0; i < 4; i++) {
            uint32_t h0, l0, h1, l1;
            split2(pf[i].x, pf[i].y, h0, l0);
            split2(pf[i].z, pf[i].w, h1, l1);
            const uint32_t ad = st + arow * A_PITCH + (aq * 16 + 4 * i) * 2;
            sts8(ad,        h0, h1);
            sts8(ad + A_TB, l0, l1);
        }
    };
    auto cpB = [&](int c, int s) {
        const uint32_t st = smb + s * STAGE_B + 2 * A_TB;
        #pragma unroll
        for (int i = 0; i < 4; i++) {
            const int idx  = tid + i * 256;
            const int tile = idx >> 9;
            const int r    = (idx >> 4) & 31;
            const int g    = idx & 15;
            const __nv_bfloat16* src =
                (tile ? Blo : Bhi) + (size_t)(c * 32 + r) * N + n0 + g * 8;
            cp_async16(st + tile * B_TB + r * B_PITCH + g * 16, src);
        }
        cp_commit();
    };

    float acc[4][4][4];
    #pragma unroll
    for (int a = 0; a < 4; a++)
        #pragma unroll
        for (int b = 0; b < 4; b++)
            #pragma unroll
            for (int r = 0; r < 4; r++) acc[a][b][r] = 0.f;

    ldgA(0);
    cpB(0, 0);
    stsA(0);
    cp_wait<0>();
    __syncthreads();

    for (int c = 0; c < nc; c++) {
        if (c + 1 < nc) { ldgA(c + 1); cpB(c + 1, (c + 1) & 1); }

        const uint32_t stage = smb + (c & 1) * STAGE_B;
        const uint32_t sAh = stage, sAl = stage + A_TB;
        const uint32_t sBh = stage + 2 * A_TB, sBl = sBh + B_TB;

        #pragma unroll
        for (int ks = 0; ks < 2; ks++) {
            uint32_t ah[4][4], al[4][4];
            const uint32_t acb = ks * 32 + ((lane >> 4) * 16);
            #pragma unroll
            for (int mt = 0; mt < 4; mt++) {
                const uint32_t ro = (wm * 64 + mt * 16 + (lane & 15)) * A_PITCH + acb;
                ldm_x4(ah[mt], sAh + ro);
                ldm_x4(al[mt], sAl + ro);
            }
            const uint32_t brow16 = (ks * 16 + (lane & 15)) * B_PITCH;
            #pragma unroll
            for (int nt = 0; nt < 4; nt++) {
                const uint32_t co = (wn * 32 + nt * 8) * 2;
                uint32_t bh[2], bl[2];
                ldm_x2_trans(bh, sBh + brow16 + co);
                ldm_x2_trans(bl, sBl + brow16 + co);
                #pragma unroll
                for (int mt = 0; mt < 4; mt++) {
                    mma_bf16(acc[mt][nt], ah[mt], bh);
                    mma_bf16(acc[mt][nt], ah[mt], bl);
                    mma_bf16(acc[mt][nt], al[mt], bh);
                }
            }
        }

        if (c + 1 < nc) stsA((c + 1) & 1);
        cp_wait<0>();
        __syncthreads();
    }

    if (silu_mode) {
        // cols interleaved in 8-groups: even group = w1, odd group = w3 (pairwise)
        const int No = N >> 1;
        #pragma unroll
        for (int mt = 0; mt < 4; mt++) {
            #pragma unroll
            for (int np = 0; np < 2; np++) {
                const int nt = np * 2;
                const int col1 = n0 + wn * 32 + nt * 8 + (lane & 3) * 2;
                const int nf = ((col1 >> 4) << 3) + (col1 & 7);
                #pragma unroll
                for (int hh = 0; hh < 2; hh++) {
                    const int row = m0 + wm * 64 + mt * 16 + (lane >> 2) + hh * 8;
                    #pragma unroll
                    for (int jj = 0; jj < 2; jj++) {
                        const float a = acc[mt][nt][hh * 2 + jj];
                        const float g = acc[mt][nt + 1][hh * 2 + jj];
                        C[(size_t)row * No + nf + jj] =
                            (a / (1.0f + __expf(-a))) * g;
                    }
                }
            }
        }
    } else {
        #pragma unroll
        for (int mt = 0; mt < 4; mt++) {
            #pragma unroll
            for (int nt = 0; nt < 4; nt++) {
                const int col = n0 + wn * 32 + nt * 8 + (lane & 3) * 2;
                float bv0 = 0.f, bv1 = 0.f;
                if (bias) { bv0 = bias[col]; bv1 = bias[col + 1]; }
                #pragma unroll
                for (int hh = 0; hh < 2; hh++) {
                    const int row = m0 + wm * 64 + mt * 16 + (lane >> 2) + hh * 8;
                    float v0 = acc[mt][nt][hh * 2]     + bv0;
                    float v1 = acc[mt][nt][hh * 2 + 1] + bv1;
                    const size_t off = (size_t)row * N + col;
                    if (res) { v0 += res[off]; v1 += res[off + 1]; }
                    C[off]     = v0;
                    C[off + 1] = v1;
                }
            }
        }
    }
}

// ======================= RMSNorm =============================================
__global__ void rmsnorm_kernel(const float* __restrict__ x,
                               const float* __restrict__ w,
                               float* __restrict__ out)
{
    const int row = blockIdx.x;
    const float* xr = x + (size_t)row * DMODEL;
    float s = 0.f;
    for (int i = threadIdx.x; i < DMODEL; i += 256) { float v = xr[i]; s += v * v; }
    #pragma unroll
    for (int off = 16; off; off >>= 1) s += __shfl_down_sync(0xffffffffu, s, off);
    __shared__ float red[8];
    const int warp = threadIdx.x >> 5, lane = threadIdx.x & 31;
    if (lane == 0) red[warp] = s;
    __syncthreads();
    if (warp == 0) {
        float t = (lane < 8) ? red[lane] : 0.f;
        #pragma unroll
        for (int off = 4; off; off >>= 1) t += __shfl_down_sync(0xffu, t, off);
        if (lane == 0) red[0] = t;
    }
    __syncthreads();
    const float inv = rsqrtf(red[0] * (1.0f / DMODEL) + 1e-5f);
    for (int i = threadIdx.x; i < DMODEL; i += 256)
        out[(size_t)row * DMODEL + i] = xr[i] * inv * w[i];
}

// ======================= tiled local attention (rope fused) ==================
#define AT_PAD   65
#define AT_TILE  (64 * AT_PAD)
#define ATTN_SMEM (4 * AT_TILE * 4)

__global__ void __launch_bounds__(256)
attn_kernel(const float* __restrict__ qkv,
            const int* __restrict__ doc_id,
            const int* __restrict__ tok_id,
            const float* __restrict__ ct,
            const float* __restrict__ st,
            float* __restrict__ o)
{
    extern __shared__ float as_[];
    float* Qs = as_;
    float* Ks = Qs + AT_TILE;
    float* Vs = Ks + AT_TILE;
    float* Sc = Vs + AT_TILE;

    const int q0 = blockIdx.x * 64;
    const int h  = blockIdx.y;
    const int tid = threadIdx.x;
    const int q = tid >> 2, quad = tid & 3;

    // load Q tile with inline rope
    #pragma unroll
    for (int j = 0; j < 16; j++) {
        const int e = tid + j * 256;
        const int r = e >> 6, cl = e & 63;
        const int s = q0 + r;
        const size_t base = (size_t)s * 3072 + h * HDIM;
        const int i = cl & 31;
        const float c = ct[s * 32 + i], sn = st[s * 32 + i];
        const float x1 = qkv[base + i], x2 = qkv[base + 32 + i];
        Qs[r * AT_PAD + cl] = (cl < 32) ? (x1 * c - x2 * sn) : (x1 * sn + x2 * c);
    }

    const int myS = q0 + q;
    const int myDoc = doc_id[myS], myTok = tok_id[myS];

    float m = -1e29f, l = 0.f, O[16];
    #pragma unroll
    for (int j = 0; j < 16; j++) O[j] = 0.f;

    float qr[16];
    __syncthreads();
    #pragma unroll
    for (int j = 0; j < 16; j++) qr[j] = Qs[q * AT_PAD + quad * 16 + j];

    const int kbase0 = q0 - 128;
    for (int ch = 0; ch < 5; ch++) {
        const int kb = kbase0 + ch * 64;
        __syncthreads();
        #pragma unroll
        for (int j = 0; j < 16; j++) {
            const int e = tid + j * 256;
            const int r = e >> 6, cl = e & 63;
            const int kg = kb + r;
            const bool in = (kg >= 0) & (kg < SLEN);
            const int ks = in ? kg : 0;
            const size_t base = (size_t)ks * 3072 + h * HDIM;
            const int i = cl & 31;
            const float c = ct[ks * 32 + i], sn = st[ks * 32 + i];
            const float x1 = qkv[base + 1024 + i], x2 = qkv[base + 1056 + i];
            const float kvv = (cl < 32) ? (x1 * c - x2 * sn) : (x1 * sn + x2 * c);
            Ks[r * AT_PAD + cl] = in ? kvv : 0.f;
            Vs[r * AT_PAD + cl] = in ? qkv[base + 2048 + cl] : 0.f;
        }
        __syncthreads();

        // full dots: thread (q, quad) handles k = quad + kk*4
        #pragma unroll 4
        for (int kk = 0; kk < 16; kk++) {
            const int k = quad + kk * 4;
            float p = 0.f;
            #pragma unroll
            for (int j = 0; j < 16; j++)
                p += qr[j] * Ks[k * AT_PAD + quad * 16 + j];
            #pragma unroll
            for (int qd = 0; qd < 4; qd++) {
                if (qd == quad) continue;
                #pragma unroll
                for (int j = 0; j < 16; j++)
                    p += Qs[q * AT_PAD + qd * 16 + j] * Ks[k * AT_PAD + qd * 16 + j];
            }
            const int kg = kb + k;
            bool ok = (kg >= 0) && (kg < SLEN);
            if (ok) ok = (doc_id[kg] == myDoc) && (abs(tok_id[kg] - myTok) < 128);
            Sc[q * AT_PAD + k] = ok ? p * 0.125f : -1e30f;
        }
        __syncthreads();

        float cm = -1e30f;
        #pragma unroll 8
        for (int k = 0; k < 64; k++) cm = fmaxf(cm, Sc[q * AT_PAD + k]);
        const float mn = fmaxf(m, cm);
        const float scale = __expf(m - mn);
        l *= scale;
        #pragma unroll
        for (int j = 0; j < 16; j++) O[j] *= scale;
        #pragma unroll 4
        for (int k = 0; k < 64; k++) {
            const float p = __expf(Sc[q * AT_PAD + k] - mn);
            l += p;
            #pragma unroll
            for (int j = 0; j < 16; j++)
                O[j] += p * Vs[k * AT_PAD + quad * 16 + j];
        }
        m = mn;
    }

    const float inv = 1.0f / l;
    #pragma unroll
    for (int j = 0; j < 16; j++)
        o[(size_t)myS * DMODEL + h * HDIM + quad * 16 + j] = O[j] * inv;
}

// ======================= launch ==============================================
static void run_gemm(const float* A, const __nv_bfloat16* Bhi, const __nv_bfloat16* Blo,
                     const float* bias, const float* res, float* C,
                     int M, int N, int K, int Ap, int silu = 0)
{
    dim3 g(N / 128, M / 128);
    hgemm_kernel<<<g, 256, HG_SMEM>>>(A, Bhi, Blo, bias, res, C, M, N, K, Ap, silu);
}

static int add_seg(WTab& t, int& blk, const float* W, unsigned dstoff,
                   int K, int Nsrc, int P, int c0, int grp)
{
    const int t4 = K * Nsrc / 4;
    WSeg& s = t.s[t.nseg++];
    s.W = W; s.dstoff = dstoff; s.Nsrc = Nsrc; s.P = P;
    s.c0 = c0; s.grp = grp; s.t4 = t4; s.blk0 = blk;
    blk += (t4 + 255) / 256;
    return blk;
}

extern "C" void kernel_launch(void* const* d_in, const int* in_sizes, int n_in,
                              void* d_out, int out_size)
{
    const float* x           = (const float*)d_in[0];
    const float* emb_w       = (const float*)d_in[1];
    const float* emb_b       = (const float*)d_in[2];
    const float* wq          = (const float*)d_in[3];
    const float* wk          = (const float*)d_in[4];
    const float* wv          = (const float*)d_in[5];
    const float* wo          = (const float*)d_in[6];
    const float* attn_norm_w = (const float*)d_in[7];
    const float* ffn_norm_w  = (const float*)d_in[8];
    const float* w1          = (const float*)d_in[9];
    const float* w2          = (const float*)d_in[10];
    const float* w3          = (const float*)d_in[11];
    const float* out_norm_w  = (const float*)d_in[12];
    const float* out_w       = (const float*)d_in[13];
    const int*   doc_id      = (const int*)d_in[14];
    const int*   tok_id      = (const int*)d_in[15];
    float* out = (float*)d_out;

    cudaFuncSetAttribute(hgemm_kernel,
                         cudaFuncAttributeMaxDynamicSharedMemorySize, HG_SMEM);
    cudaFuncSetAttribute(attn_kernel,
                         cudaFuncAttributeMaxDynamicSharedMemorySize, ATTN_SMEM);

    float *h, *hn, *qkv, *o, *f, *ct, *st;
    __nv_bfloat16 *whi, *wlo;
    cudaGetSymbolAddress((void**)&h,   g_h);
    cudaGetSymbolAddress((void**)&hn,  g_hn);
    cudaGetSymbolAddress((void**)&qkv, g_qkv);
    cudaGetSymbolAddress((void**)&o,   g_o);
    cudaGetSymbolAddress((void**)&f,   g_f);
    cudaGetSymbolAddress((void**)&ct,  g_ct);
    cudaGetSymbolAddress((void**)&st,  g_st);
    cudaGetSymbolAddress((void**)&whi, g_whi);
    cudaGetSymbolAddress((void**)&wlo, g_wlo);

    // launch 0: trig table
    trig_kernel<<<(SLEN * 32 + 255) / 256, 256>>>(tok_id, ct, st);

    // launches 1,2: batched weight split (two halves)
    for (int halfi = 0; halfi < 2; halfi++) {
        WTab t;
        t.nseg = 0;
        int blk = 0;
        if (halfi == 0)
            add_seg(t, blk, emb_w, 0, IND, DMODEL, DMODEL, 0, 0);
        for (int l = halfi * 2; l < halfi * 2 + 2; l++) {
            const unsigned lb = OFF_L + (unsigned)l * LSTR;
            const size_t wqo = (size_t)l * DMODEL * DMODEL;
            const size_t wfo = (size_t)l * DMODEL * FFND;
            add_seg(t, blk, wq + wqo, lb,            DMODEL, DMODEL, 3072, 0,    0);
            add_seg(t, blk, wk + wqo, lb,            DMODEL, DMODEL, 3072, 1024, 0);
            add_seg(t, blk, wv + wqo, lb,            DMODEL, DMODEL, 3072, 2048, 0);
            add_seg(t, blk, wo + wqo, lb + 3145728,  DMODEL, DMODEL, 1024, 0,    0);
            add_seg(t, blk, w1 + wfo, lb + 4194304,  DMODEL, FFND,   8192, 0,    1);
            add_seg(t, blk, w3 + wfo, lb + 4194304,  DMODEL, FFND,   8192, 8,    1);
            add_seg(t, blk, w2 + wfo, lb + 12582912, FFND,   DMODEL, 1024, 0,    0);
        }
        if (halfi == 1)
            add_seg(t, blk, out_w, OFF_OUT, DMODEL, OUTD, OUTD, 0, 0);
        wsplit_all<<<blk, 256>>>(t, whi, wlo);
    }

    // launch 3: embedding
    run_gemm(x, whi, wlo, emb_b, nullptr, h, SLEN, DMODEL, IND, IND);

    for (int l = 0; l < NLAYER; l++) {
        const __nv_bfloat16* hb = whi + OFF_L + (size_t)l * LSTR;
        const __nv_bfloat16* lb = wlo + OFF_L + (size_t)l * LSTR;

        rmsnorm_kernel<<<SLEN, 256>>>(h, attn_norm_w + (size_t)l * DMODEL, hn);
        // on l==0 this is launch 5 -> ncu capture target
        run_gemm(hn, hb, lb, nullptr, nullptr, qkv, SLEN, 3072, DMODEL, DMODEL);
        attn_kernel<<<dim3(SLEN / 64, NH), 256, ATTN_SMEM>>>(qkv, doc_id, tok_id,
                                                             ct, st, o);
        run_gemm(o, hb + 3145728, lb + 3145728, nullptr, h, h,
                 SLEN, DMODEL, DMODEL, DMODEL);

        rmsnorm_kernel<<<SLEN, 256>>>(h, ffn_norm_w + (size_t)l * DMODEL, hn);
        run_gemm(hn, hb + 4194304, lb + 4194304, nullptr, nullptr, f,
                 SLEN, 2 * FFND, DMODEL, DMODEL, 1);
        run_gemm(f, hb + 12582912, lb + 12582912, nullptr, h, h,
                 SLEN, DMODEL, FFND, FFND);
    }

    rmsnorm_kernel<<<SLEN, 256>>>(h, out_norm_w, hn);
    run_gemm(hn, whi + OFF_OUT, wlo + OFF_OUT, nullptr, nullptr, out,
             SLEN, OUTD, DMODEL, DMODEL);
}

// round 10
// speedup vs baseline: 1.5477x; 1.1513x over previous
#include <cuda_runtime.h>
#include <cuda_bf16.h>
#include <math.h>
#include <stdint.h>

#define SLEN   2048
#define DMODEL 1024
#define NH     16
#define HDIM   64
#define NLAYER 4
#define FFND   4096
#define OUTD   128
#define IND    64

// ======================= helpers =============================================
__device__ __forceinline__ uint32_t smem_u32(const void* p) {
    uint32_t a;
    asm("{ .reg .u64 t; cvta.to.shared.u64 t, %1; cvt.u32.u64 %0, t; }"
        : "=r"(a) : "l"(p));
    return a;
}
__device__ __forceinline__ void cp_async16(uint32_t dst, const void* src) {
    asm volatile("cp.async.cg.shared.global [%0], [%1], 16;" :: "r"(dst), "l"(src));
}
__device__ __forceinline__ void cp_commit() {
    asm volatile("cp.async.commit_group;" ::: "memory");
}
template <int NN> __device__ __forceinline__ void cp_wait() {
    asm volatile("cp.async.wait_group %0;" :: "n"(NN) : "memory");
}
__device__ __forceinline__ void ldm_x4(uint32_t* r, uint32_t addr) {
    asm volatile("ldmatrix.sync.aligned.m8n8.x4.shared.b16 {%0,%1,%2,%3}, [%4];"
                 : "=r"(r[0]), "=r"(r[1]), "=r"(r[2]), "=r"(r[3]) : "r"(addr));
}
__device__ __forceinline__ void ldm_x2_trans(uint32_t* r, uint32_t addr) {
    asm volatile("ldmatrix.sync.aligned.m8n8.x2.trans.shared.b16 {%0,%1}, [%2];"
                 : "=r"(r[0]), "=r"(r[1]) : "r"(addr));
}
__device__ __forceinline__ void mma_bf16(float* c, const uint32_t* a, const uint32_t* b) {
    asm volatile(
        "mma.sync.aligned.m16n8k16.row.col.f32.bf16.bf16.f32 "
        "{%0,%1,%2,%3}, {%4,%5,%6,%7}, {%8,%9}, {%0,%1,%2,%3};"
        : "+f"(c[0]), "+f"(c[1]), "+f"(c[2]), "+f"(c[3])
        : "r"(a[0]), "r"(a[1]), "r"(a[2]), "r"(a[3]), "r"(b[0]), "r"(b[1]));
}
__device__ __forceinline__ void split2(float x, float y, uint32_t& h, uint32_t& l) {
    __nv_bfloat16 hx = __float2bfloat16(x), hy = __float2bfloat16(y);
    __nv_bfloat16 lx = __float2bfloat16(x - __bfloat162float(hx));
    __nv_bfloat16 ly = __float2bfloat16(y - __bfloat162float(hy));
    __nv_bfloat162 hp = __halves2bfloat162(hx, hy);
    __nv_bfloat162 lp = __halves2bfloat162(lx, ly);
    h = *reinterpret_cast<uint32_t*>(&hp);
    l = *reinterpret_cast<uint32_t*>(&lp);
}
__device__ __forceinline__ uint32_t split1(float x, __nv_bfloat16* lo) {
    __nv_bfloat16 hx = __float2bfloat16(x);
    *lo = __float2bfloat16(x - __bfloat162float(hx));
    return 0;
}

// ======================= scratch =============================================
#define LSTR    16777216u
#define OFF_L   65536u
#define OFF_OUT (65536u + 4u * LSTR)
#define WTOT    (OFF_OUT + 131072u)
__device__ __nv_bfloat16 g_whi[WTOT];
__device__ __nv_bfloat16 g_wlo[WTOT];

__device__ float g_h  [SLEN * DMODEL];
__device__ float g_qkv[SLEN * 3 * DMODEL];
__device__ float g_ct [SLEN * 32];
__device__ float g_st [SLEN * 32];
__device__ __nv_bfloat16 g_hn_hi[SLEN * DMODEL];
__device__ __nv_bfloat16 g_hn_lo[SLEN * DMODEL];
__device__ __nv_bfloat16 g_o_hi [SLEN * DMODEL];
__device__ __nv_bfloat16 g_o_lo [SLEN * DMODEL];
__device__ __nv_bfloat16 g_f_hi [SLEN * FFND];
__device__ __nv_bfloat16 g_f_lo [SLEN * FFND];
__device__ __nv_bfloat16 g_x_hi [SLEN * IND];
__device__ __nv_bfloat16 g_x_lo [SLEN * IND];

// =============== init: trig table + x hi/lo split (one kernel) ===============
__global__ void init_kernel(const int* __restrict__ tok_id,
                            const float* __restrict__ x,
                            float* __restrict__ ct, float* __restrict__ st,
                            __nv_bfloat16* __restrict__ xhi,
                            __nv_bfloat16* __restrict__ xlo)
{
    const int idx = blockIdx.x * blockDim.x + threadIdx.x;
    if (idx < SLEN * 32) {
        const int i = idx & 31, s = idx >> 5;
        const double inv = pow(10000.0, -(double)i / 32.0);
        const double ang = (double)tok_id[s] * inv;
        double sd, cd;
        sincos(ang, &sd, &cd);
        ct[idx] = (float)cd;
        st[idx] = (float)sd;
    } else {
        const int i = idx - SLEN * 32;
        if (i < SLEN * IND / 4) {
            const float4 v = ((const float4*)x)[i];
            uint32_t h0, l0, h1, l1;
            split2(v.x, v.y, h0, l0);
            split2(v.z, v.w, h1, l1);
            ((uint2*)xhi)[i] = make_uint2(h0, h1);
            ((uint2*)xlo)[i] = make_uint2(l0, l1);
        }
    }
}

// ======================= batched weight split ================================
struct WSeg {
    const float* W;
    unsigned dstoff;
    int Nsrc, P, c0, grp, t4, blk0;
};
struct WTab { WSeg s[15]; int nseg; };

__global__ void __launch_bounds__(256)
wsplit_all(WTab t, __nv_bfloat16* __restrict__ hi, __nv_bfloat16* __restrict__ lo)
{
    const int b = blockIdx.x;
    int si = 0;
    #pragma unroll 1
    for (int j = 1; j < t.nseg; j++) if (b >= t.s[j].blk0) si = j;
    const WSeg sg = t.s[si];
    const int i = (b - sg.blk0) * 256 + threadIdx.x;
    if (i >= sg.t4) return;
    const int e = i * 4;
    const int k = e / sg.Nsrc, n = e - k * sg.Nsrc;
    const float4 v = *(const float4*)(sg.W + e);
    uint32_t h0, l0, h1, l1;
    split2(v.x, v.y, h0, l0);
    split2(v.z, v.w, h1, l1);
    const int col = sg.grp ? (((n >> 3) << 4) + (n & 7) + sg.c0) : (sg.c0 + n);
    const size_t d = sg.dstoff + (size_t)k * sg.P + col;
    *(uint2*)(hi + d) = make_uint2(h0, h1);
    *(uint2*)(lo + d) = make_uint2(l0, l1);
}

// ============ HMMA GEMM: all-bf16 operands, cp.async only ====================
// C[M,N] = A[M,K] @ B[K,N]; A,B pre-split bf16 hi/lo.
// 3 passes: AhBh + AhBl + AlBh. CTA 128x128, 8 warps, K-chunk 32, 2 stages.
#define A_PITCH 80
#define B_PITCH 272
#define A_TB    (128 * A_PITCH)        // 10240
#define B_TB    (32 * B_PITCH)         // 8704
#define STAGE_B (2 * A_TB + 2 * B_TB)  // 37888
#define HG_SMEM (2 * STAGE_B)

__global__ void __launch_bounds__(256, 2)
hgemm_kernel(const __nv_bfloat16* __restrict__ Ahi,
             const __nv_bfloat16* __restrict__ Alo,
             const __nv_bfloat16* __restrict__ Bhi,
             const __nv_bfloat16* __restrict__ Blo,
             const float* __restrict__ bias,
             const float* __restrict__ res,
             float* __restrict__ C,
             __nv_bfloat16* __restrict__ Chi,
             __nv_bfloat16* __restrict__ Clo,
             int M, int N, int K, int Ap, int silu_mode)
{
    extern __shared__ char sm[];
    const uint32_t smb = smem_u32(sm);

    const int tid  = threadIdx.x;
    const int wid  = tid >> 5, lane = tid & 31;
    const int wm   = wid >> 2;
    const int wn   = wid & 3;
    const int m0 = blockIdx.y * 128, n0 = blockIdx.x * 128;
    const int nc = K >> 5;

    auto cpA = [&](int c, int s) {
        const uint32_t st = smb + s * STAGE_B;
        #pragma unroll
        for (int i = 0; i < 4; i++) {
            const int idx  = tid + i * 256;
            const int tile = idx >> 9;
            const int r    = (idx >> 2) & 127;
            const int g    = idx & 3;
            const __nv_bfloat16* src =
                (tile ? Alo : Ahi) + (size_t)(m0 + r) * Ap + c * 32 + g * 8;
            cp_async16(st + tile * A_TB + r * A_PITCH + g * 16, src);
        }
    };
    auto cpB = [&](int c, int s) {
        const uint32_t st = smb + s * STAGE_B + 2 * A_TB;
        #pragma unroll
        for (int i = 0; i < 4; i++) {
            const int idx  = tid + i * 256;
            const int tile = idx >> 9;
            const int r    = (idx >> 4) & 31;
            const int g    = idx & 15;
            const __nv_bfloat16* src =
                (tile ? Blo : Bhi) + (size_t)(c * 32 + r) * N + n0 + g * 8;
            cp_async16(st + tile * B_TB + r * B_PITCH + g * 16, src);
        }
    };

    float acc[4][4][4];
    #pragma unroll
    for (int a = 0; a < 4; a++)
        #pragma unroll
        for (int b = 0; b < 4; b++)
            #pragma unroll
            for (int r = 0; r < 4; r++) acc[a][b][r] = 0.f;

    cpA(0, 0);
    cpB(0, 0);
    cp_commit();
    cp_wait<0>();
    __syncthreads();

    for (int c = 0; c < nc; c++) {
        if (c + 1 < nc) { cpA(c + 1, (c + 1) & 1); cpB(c + 1, (c + 1) & 1); cp_commit(); }

        const uint32_t stage = smb + (c & 1) * STAGE_B;
        const uint32_t sAh = stage, sAl = stage + A_TB;
        const uint32_t sBh = stage + 2 * A_TB, sBl = sBh + B_TB;

        #pragma unroll
        for (int ks = 0; ks < 2; ks++) {
            uint32_t ah[4][4], al[4][4];
            const uint32_t acb = ks * 32 + ((lane >> 4) * 16);
            #pragma unroll
            for (int mt = 0; mt < 4; mt++) {
                const uint32_t ro = (wm * 64 + mt * 16 + (lane & 15)) * A_PITCH + acb;
                ldm_x4(ah[mt], sAh + ro);
                ldm_x4(al[mt], sAl + ro);
            }
            const uint32_t brow16 = (ks * 16 + (lane & 15)) * B_PITCH;
            #pragma unroll
            for (int nt = 0; nt < 4; nt++) {
                const uint32_t co = (wn * 32 + nt * 8) * 2;
                uint32_t bh[2], bl[2];
                ldm_x2_trans(bh, sBh + brow16 + co);
                ldm_x2_trans(bl, sBl + brow16 + co);
                #pragma unroll
                for (int mt = 0; mt < 4; mt++) {
                    mma_bf16(acc[mt][nt], ah[mt], bh);
                    mma_bf16(acc[mt][nt], ah[mt], bl);
                    mma_bf16(acc[mt][nt], al[mt], bh);
                }
            }
        }

        cp_wait<0>();
        __syncthreads();
    }

    if (silu_mode) {
        const int No = N >> 1;
        #pragma unroll
        for (int mt = 0; mt < 4; mt++) {
            #pragma unroll
            for (int np = 0; np < 2; np++) {
                const int nt = np * 2;
                const int col1 = n0 + wn * 32 + nt * 8 + (lane & 3) * 2;
                const int nf = ((col1 >> 4) << 3) + (col1 & 7);
                #pragma unroll
                for (int hh = 0; hh < 2; hh++) {
                    const int row = m0 + wm * 64 + mt * 16 + (lane >> 2) + hh * 8;
                    float v0, v1;
                    {
                        const float a = acc[mt][nt][hh * 2];
                        v0 = (a / (1.0f + __expf(-a))) * acc[mt][nt + 1][hh * 2];
                        const float b = acc[mt][nt][hh * 2 + 1];
                        v1 = (b / (1.0f + __expf(-b))) * acc[mt][nt + 1][hh * 2 + 1];
                    }
                    uint32_t hw, lw;
                    split2(v0, v1, hw, lw);
                    const size_t off = (size_t)row * No + nf;
                    *(uint32_t*)(Chi + off) = hw;
                    *(uint32_t*)(Clo + off) = lw;
                }
            }
        }
    } else {
        #pragma unroll
        for (int mt = 0; mt < 4; mt++) {
            #pragma unroll
            for (int nt = 0; nt < 4; nt++) {
                const int col = n0 + wn * 32 + nt * 8 + (lane & 3) * 2;
                float bv0 = 0.f, bv1 = 0.f;
                if (bias) { bv0 = bias[col]; bv1 = bias[col + 1]; }
                #pragma unroll
                for (int hh = 0; hh < 2; hh++) {
                    const int row = m0 + wm * 64 + mt * 16 + (lane >> 2) + hh * 8;
                    float v0 = acc[mt][nt][hh * 2]     + bv0;
                    float v1 = acc[mt][nt][hh * 2 + 1] + bv1;
                    const size_t off = (size_t)row * N + col;
                    if (res) { v0 += res[off]; v1 += res[off + 1]; }
                    C[off]     = v0;
                    C[off + 1] = v1;
                }
            }
        }
    }
}

// ======================= RMSNorm (bf16 hi/lo output) =========================
__global__ void rmsnorm_kernel(const float* __restrict__ x,
                               const float* __restrict__ w,
                               __nv_bfloat16* __restrict__ ohi,
                               __nv_bfloat16* __restrict__ olo)
{
    const int row = blockIdx.x;
    const float* xr = x + (size_t)row * DMODEL;
    float s = 0.f;
    for (int i = threadIdx.x; i < DMODEL; i += 256) { float v = xr[i]; s += v * v; }
    #pragma unroll
    for (int off = 16; off; off >>= 1) s += __shfl_down_sync(0xffffffffu, s, off);
    __shared__ float red[8];
    const int warp = threadIdx.x >> 5, lane = threadIdx.x & 31;
    if (lane == 0) red[warp] = s;
    __syncthreads();
    if (warp == 0) {
        float t = (lane < 8) ? red[lane] : 0.f;
        #pragma unroll
        for (int off = 4; off; off >>= 1) t += __shfl_down_sync(0xffu, t, off);
        if (lane == 0) red[0] = t;
    }
    __syncthreads();
    const float inv = rsqrtf(red[0] * (1.0f / DMODEL) + 1e-5f);
    for (int i = threadIdx.x * 2; i < DMODEL; i += 512) {
        const float v0 = xr[i] * inv * w[i];
        const float v1 = xr[i + 1] * inv * w[i + 1];
        uint32_t hw, lw;
        split2(v0, v1, hw, lw);
        const size_t d = (size_t)row * DMODEL + i;
        *(uint32_t*)(ohi + d) = hw;
        *(uint32_t*)(olo + d) = lw;
    }
}

// ======================= tiled local attention (rope fused, bf16 out) ========
#define AT_PAD   65
#define AT_TILE  (64 * AT_PAD)
#define ATTN_SMEM (4 * AT_TILE * 4)

__global__ void __launch_bounds__(256)
attn_kernel(const float* __restrict__ qkv,
            const int* __restrict__ doc_id,
            const int* __restrict__ tok_id,
            const float* __restrict__ ct,
            const float* __restrict__ st,
            __nv_bfloat16* __restrict__ ohi,
            __nv_bfloat16* __restrict__ olo)
{
    extern __shared__ float as_[];
    float* Qs = as_;
    float* Ks = Qs + AT_TILE;
    float* Vs = Ks + AT_TILE;
    float* Sc = Vs + AT_TILE;

    const int q0 = blockIdx.x * 64;
    const int h  = blockIdx.y;
    const int tid = threadIdx.x;
    const int q = tid >> 2, quad = tid & 3;

    #pragma unroll
    for (int j = 0; j < 16; j++) {
        const int e = tid + j * 256;
        const int r = e >> 6, cl = e & 63;
        const int s = q0 + r;
        const size_t base = (size_t)s * 3072 + h * HDIM;
        const int i = cl & 31;
        const float c = ct[s * 32 + i], sn = st[s * 32 + i];
        const float x1 = qkv[base + i], x2 = qkv[base + 32 + i];
        Qs[r * AT_PAD + cl] = (cl < 32) ? (x1 * c - x2 * sn) : (x1 * sn + x2 * c);
    }

    const int myS = q0 + q;
    const int myDoc = doc_id[myS], myTok = tok_id[myS];

    float m = -1e29f, l = 0.f, O[16];
    #pragma unroll
    for (int j = 0; j < 16; j++) O[j] = 0.f;

    float qr[16];
    __syncthreads();
    #pragma unroll
    for (int j = 0; j < 16; j++) qr[j] = Qs[q * AT_PAD + quad * 16 + j];

    const int kbase0 = q0 - 128;
    for (int ch = 0; ch < 5; ch++) {
        const int kb = kbase0 + ch * 64;
        __syncthreads();
        #pragma unroll
        for (int j = 0; j < 16; j++) {
            const int e = tid + j * 256;
            const int r = e >> 6, cl = e & 63;
            const int kg = kb + r;
            const bool in = (kg >= 0) & (kg < SLEN);
            const int ks = in ? kg : 0;
            const size_t base = (size_t)ks * 3072 + h * HDIM;
            const int i = cl & 31;
            const float c = ct[ks * 32 + i], sn = st[ks * 32 + i];
            const float x1 = qkv[base + 1024 + i], x2 = qkv[base + 1056 + i];
            const float kvv = (cl < 32) ? (x1 * c - x2 * sn) : (x1 * sn + x2 * c);
            Ks[r * AT_PAD + cl] = in ? kvv : 0.f;
            Vs[r * AT_PAD + cl] = in ? qkv[base + 2048 + cl] : 0.f;
        }
        __syncthreads();

        #pragma unroll 4
        for (int kk = 0; kk < 16; kk++) {
            const int k = quad + kk * 4;
            float p = 0.f;
            #pragma unroll
            for (int j = 0; j < 16; j++)
                p += qr[j] * Ks[k * AT_PAD + quad * 16 + j];
            #pragma unroll
            for (int qd = 0; qd < 4; qd++) {
                if (qd == quad) continue;
                #pragma unroll
                for (int j = 0; j < 16; j++)
                    p += Qs[q * AT_PAD + qd * 16 + j] * Ks[k * AT_PAD + qd * 16 + j];
            }
            const int kg = kb + k;
            bool ok = (kg >= 0) && (kg < SLEN);
            if (ok) ok = (doc_id[kg] == myDoc) && (abs(tok_id[kg] - myTok) < 128);
            Sc[q * AT_PAD + k] = ok ? p * 0.125f : -1e30f;
        }
        __syncthreads();

        float cm = -1e30f;
        #pragma unroll 8
        for (int k = 0; k < 64; k++) cm = fmaxf(cm, Sc[q * AT_PAD + k]);
        const float mn = fmaxf(m, cm);
        const float scale = __expf(m - mn);
        l *= scale;
        #pragma unroll
        for (int j = 0; j < 16; j++) O[j] *= scale;
        #pragma unroll 4
        for (int k = 0; k < 64; k++) {
            const float p = __expf(Sc[q * AT_PAD + k] - mn);
            l += p;
            #pragma unroll
            for (int j = 0; j < 16; j++)
                O[j] += p * Vs[k * AT_PAD + quad * 16 + j];
        }
        m = mn;
    }

    const float inv = 1.0f / l;
    const size_t base = (size_t)myS * DMODEL + h * HDIM + quad * 16;
    #pragma unroll
    for (int j = 0; j < 8; j++) {
        uint32_t hw, lw;
        split2(O[2 * j] * inv, O[2 * j + 1] * inv, hw, lw);
        *(uint32_t*)(ohi + base + 2 * j) = hw;
        *(uint32_t*)(olo + base + 2 * j) = lw;
    }
}

// ======================= launch ==============================================
static void run_gemm(const __nv_bfloat16* Ahi, const __nv_bfloat16* Alo,
                     const __nv_bfloat16* Bhi, const __nv_bfloat16* Blo,
                     const float* bias, const float* res, float* C,
                     __nv_bfloat16* Chi, __nv_bfloat16* Clo,
                     int M, int N, int K, int Ap, int silu = 0)
{
    dim3 g(N / 128, M / 128);
    hgemm_kernel<<<g, 256, HG_SMEM>>>(Ahi, Alo, Bhi, Blo, bias, res, C, Chi, Clo,
                                      M, N, K, Ap, silu);
}

static int add_seg(WTab& t, int& blk, const float* W, unsigned dstoff,
                   int K, int Nsrc, int P, int c0, int grp)
{
    const int t4 = K * Nsrc / 4;
    WSeg& s = t.s[t.nseg++];
    s.W = W; s.dstoff = dstoff; s.Nsrc = Nsrc; s.P = P;
    s.c0 = c0; s.grp = grp; s.t4 = t4; s.blk0 = blk;
    blk += (t4 + 255) / 256;
    return blk;
}

extern "C" void kernel_launch(void* const* d_in, const int* in_sizes, int n_in,
                              void* d_out, int out_size)
{
    const float* x           = (const float*)d_in[0];
    const float* emb_w       = (const float*)d_in[1];
    const float* emb_b       = (const float*)d_in[2];
    const float* wq          = (const float*)d_in[3];
    const float* wk          = (const float*)d_in[4];
    const float* wv          = (const float*)d_in[5];
    const float* wo          = (const float*)d_in[6];
    const float* attn_norm_w = (const float*)d_in[7];
    const float* ffn_norm_w  = (const float*)d_in[8];
    const float* w1          = (const float*)d_in[9];
    const float* w2          = (const float*)d_in[10];
    const float* w3          = (const float*)d_in[11];
    const float* out_norm_w  = (const float*)d_in[12];
    const float* out_w       = (const float*)d_in[13];
    const int*   doc_id      = (const int*)d_in[14];
    const int*   tok_id      = (const int*)d_in[15];
    float* out = (float*)d_out;

    cudaFuncSetAttribute(hgemm_kernel,
                         cudaFuncAttributeMaxDynamicSharedMemorySize, HG_SMEM);
    cudaFuncSetAttribute(attn_kernel,
                         cudaFuncAttributeMaxDynamicSharedMemorySize, ATTN_SMEM);

    float *h, *qkv, *ct, *st;
    __nv_bfloat16 *whi, *wlo, *hnh, *hnl, *oh, *ol, *fh, *fl, *xh, *xl;
    cudaGetSymbolAddress((void**)&h,   g_h);
    cudaGetSymbolAddress((void**)&qkv, g_qkv);
    cudaGetSymbolAddress((void**)&ct,  g_ct);
    cudaGetSymbolAddress((void**)&st,  g_st);
    cudaGetSymbolAddress((void**)&whi, g_whi);
    cudaGetSymbolAddress((void**)&wlo, g_wlo);
    cudaGetSymbolAddress((void**)&hnh, g_hn_hi);
    cudaGetSymbolAddress((void**)&hnl, g_hn_lo);
    cudaGetSymbolAddress((void**)&oh,  g_o_hi);
    cudaGetSymbolAddress((void**)&ol,  g_o_lo);
    cudaGetSymbolAddress((void**)&fh,  g_f_hi);
    cudaGetSymbolAddress((void**)&fl,  g_f_lo);
    cudaGetSymbolAddress((void**)&xh,  g_x_hi);
    cudaGetSymbolAddress((void**)&xl,  g_x_lo);

    // launch 0: trig table + x split
    init_kernel<<<(SLEN * 32 + SLEN * IND / 4 + 255) / 256, 256>>>(
        tok_id, x, ct, st, xh, xl);

    // launches 1,2: batched weight split
    for (int halfi = 0; halfi < 2; halfi++) {
        WTab t;
        t.nseg = 0;
        int blk = 0;
        if (halfi == 0)
            add_seg(t, blk, emb_w, 0, IND, DMODEL, DMODEL, 0, 0);
        for (int l = halfi * 2; l < halfi * 2 + 2; l++) {
            const unsigned lb = OFF_L + (unsigned)l * LSTR;
            const size_t wqo = (size_t)l * DMODEL * DMODEL;
            const size_t wfo = (size_t)l * DMODEL * FFND;
            add_seg(t, blk, wq + wqo, lb,            DMODEL, DMODEL, 3072, 0,    0);
            add_seg(t, blk, wk + wqo, lb,            DMODEL, DMODEL, 3072, 1024, 0);
            add_seg(t, blk, wv + wqo, lb,            DMODEL, DMODEL, 3072, 2048, 0);
            add_seg(t, blk, wo + wqo, lb + 3145728,  DMODEL, DMODEL, 1024, 0,    0);
            add_seg(t, blk, w1 + wfo, lb + 4194304,  DMODEL, FFND,   8192, 0,    1);
            add_seg(t, blk, w3 + wfo, lb + 4194304,  DMODEL, FFND,   8192, 8,    1);
            add_seg(t, blk, w2 + wfo, lb + 12582912, FFND,   DMODEL, 1024, 0,    0);
        }
        if (halfi == 1)
            add_seg(t, blk, out_w, OFF_OUT, DMODEL, OUTD, OUTD, 0, 0);
        wsplit_all<<<blk, 256>>>(t, whi, wlo);
    }

    // launch 3: embedding  h = x @ emb_w + emb_b
    run_gemm(xh, xl, whi, wlo, emb_b, nullptr, h, nullptr, nullptr,
             SLEN, DMODEL, IND, IND);

    for (int l = 0; l < NLAYER; l++) {
        const __nv_bfloat16* hb = whi + OFF_L + (size_t)l * LSTR;
        const __nv_bfloat16* lb = wlo + OFF_L + (size_t)l * LSTR;

        // l==0: launch 4 (rmsnorm), launch 5 (qkv hgemm -> ncu target)
        rmsnorm_kernel<<<SLEN, 256>>>(h, attn_norm_w + (size_t)l * DMODEL, hnh, hnl);
        run_gemm(hnh, hnl, hb, lb, nullptr, nullptr, qkv, nullptr, nullptr,
                 SLEN, 3072, DMODEL, DMODEL);
        attn_kernel<<<dim3(SLEN / 64, NH), 256, ATTN_SMEM>>>(qkv, doc_id, tok_id,
                                                             ct, st, oh, ol);
        run_gemm(oh, ol, hb + 3145728, lb + 3145728, nullptr, h, h, nullptr, nullptr,
                 SLEN, DMODEL, DMODEL, DMODEL);

        rmsnorm_kernel<<<SLEN, 256>>>(h, ffn_norm_w + (size_t)l * DMODEL, hnh, hnl);
        run_gemm(hnh, hnl, hb + 4194304, lb + 4194304, nullptr, nullptr,
                 nullptr, fh, fl, SLEN, 2 * FFND, DMODEL, DMODEL, 1);
        run_gemm(fh, fl, hb + 12582912, lb + 12582912, nullptr, h, h, nullptr, nullptr,
                 SLEN, DMODEL, FFND, FFND);
    }

    rmsnorm_kernel<<<SLEN, 256>>>(h, out_norm_w, hnh, hnl);
    run_gemm(hnh, hnl, whi + OFF_OUT, wlo + OFF_OUT, nullptr, nullptr, out,
             nullptr, nullptr, SLEN, OUTD, DMODEL, DMODEL);
}

// round 12
// speedup vs baseline: 2.3893x; 1.5438x over previous
#include <cuda_runtime.h>
#include <cuda_bf16.h>
#include <math.h>
#include <stdint.h>

#define SLEN   2048
#define DMODEL 1024
#define NH     16
#define HDIM   64
#define NLAYER 4
#define FFND   4096
#define OUTD   128
#define IND    64

// ======================= helpers =============================================
__device__ __forceinline__ uint32_t smem_u32(const void* p) {
    uint32_t a;
    asm("{ .reg .u64 t; cvta.to.shared.u64 t, %1; cvt.u32.u64 %0, t; }"
        : "=r"(a) : "l"(p));
    return a;
}
__device__ __forceinline__ void cp_async16(uint32_t dst, const void* src) {
    asm volatile("cp.async.cg.shared.global [%0], [%1], 16;" :: "r"(dst), "l"(src));
}
__device__ __forceinline__ void cp_commit() {
    asm volatile("cp.async.commit_group;" ::: "memory");
}
template <int NN> __device__ __forceinline__ void cp_wait() {
    asm volatile("cp.async.wait_group %0;" :: "n"(NN) : "memory");
}
__device__ __forceinline__ void ldm_x4(uint32_t* r, uint32_t addr) {
    asm volatile("ldmatrix.sync.aligned.m8n8.x4.shared.b16 {%0,%1,%2,%3}, [%4];"
                 : "=r"(r[0]), "=r"(r[1]), "=r"(r[2]), "=r"(r[3]) : "r"(addr));
}
__device__ __forceinline__ void ldm_x2(uint32_t* r, uint32_t addr) {
    asm volatile("ldmatrix.sync.aligned.m8n8.x2.shared.b16 {%0,%1}, [%2];"
                 : "=r"(r[0]), "=r"(r[1]) : "r"(addr));
}
__device__ __forceinline__ void ldm_x2_trans(uint32_t* r, uint32_t addr) {
    asm volatile("ldmatrix.sync.aligned.m8n8.x2.trans.shared.b16 {%0,%1}, [%2];"
                 : "=r"(r[0]), "=r"(r[1]) : "r"(addr));
}
__device__ __forceinline__ void mma_bf16(float* c, const uint32_t* a, const uint32_t* b) {
    asm volatile(
        "mma.sync.aligned.m16n8k16.row.col.f32.bf16.bf16.f32 "
        "{%0,%1,%2,%3}, {%4,%5,%6,%7}, {%8,%9}, {%0,%1,%2,%3};"
        : "+f"(c[0]), "+f"(c[1]), "+f"(c[2]), "+f"(c[3])
        : "r"(a[0]), "r"(a[1]), "r"(a[2]), "r"(a[3]), "r"(b[0]), "r"(b[1]));
}
__device__ __forceinline__ void split2(float x, float y, uint32_t& h, uint32_t& l) {
    __nv_bfloat16 hx = __float2bfloat16(x), hy = __float2bfloat16(y);
    __nv_bfloat16 lx = __float2bfloat16(x - __bfloat162float(hx));
    __nv_bfloat16 ly = __float2bfloat16(y - __bfloat162float(hy));
    __nv_bfloat162 hp = __halves2bfloat162(hx, hy);
    __nv_bfloat162 lp = __halves2bfloat162(lx, ly);
    h = *reinterpret_cast<uint32_t*>(&hp);
    l = *reinterpret_cast<uint32_t*>(&lp);
}

// ======================= scratch =============================================
#define LSTR    16777216u
#define OFF_L   65536u
#define OFF_OUT (65536u + 4u * LSTR)
#define WTOT    (OFF_OUT + 131072u)
__device__ __nv_bfloat16 g_whi[WTOT];
__device__ __nv_bfloat16 g_wlo[WTOT];

__device__ float g_h  [SLEN * DMODEL];
__device__ float g_qkv[SLEN * 3 * DMODEL];
__device__ float g_ct [SLEN * 32];
__device__ float g_st [SLEN * 32];
__device__ __nv_bfloat16 g_hn_hi[SLEN * DMODEL];
__device__ __nv_bfloat16 g_hn_lo[SLEN * DMODEL];
__device__ __nv_bfloat16 g_o_hi [SLEN * DMODEL];
__device__ __nv_bfloat16 g_o_lo [SLEN * DMODEL];
__device__ __nv_bfloat16 g_f_hi [SLEN * FFND];
__device__ __nv_bfloat16 g_f_lo [SLEN * FFND];
__device__ __nv_bfloat16 g_x_hi [SLEN * IND];
__device__ __nv_bfloat16 g_x_lo [SLEN * IND];

// =============== init: trig table + x hi/lo split ============================
__global__ void init_kernel(const int* __restrict__ tok_id,
                            const float* __restrict__ x,
                            float* __restrict__ ct, float* __restrict__ st,
                            __nv_bfloat16* __restrict__ xhi,
                            __nv_bfloat16* __restrict__ xlo)
{
    const int idx = blockIdx.x * blockDim.x + threadIdx.x;
    if (idx < SLEN * 32) {
        const int i = idx & 31, s = idx >> 5;
        const double inv = pow(10000.0, -(double)i / 32.0);
        const double ang = (double)tok_id[s] * inv;
        double sd, cd;
        sincos(ang, &sd, &cd);
        ct[idx] = (float)cd;
        st[idx] = (float)sd;
    } else {
        const int i = idx - SLEN * 32;
        if (i < SLEN * IND / 4) {
            const float4 v = ((const float4*)x)[i];
            uint32_t h0, l0, h1, l1;
            split2(v.x, v.y, h0, l0);
            split2(v.z, v.w, h1, l1);
            ((uint2*)xhi)[i] = make_uint2(h0, h1);
            ((uint2*)xlo)[i] = make_uint2(l0, l1);
        }
    }
}

// ======================= batched weight split (8 elems/thread) ===============
struct WSeg {
    const float* W;
    unsigned dstoff;
    int Nsrc, P, c0, grp, t8, blk0;
};
struct WTab { WSeg s[15]; int nseg; };

__global__ void __launch_bounds__(256)
wsplit_all(WTab t, __nv_bfloat16* __restrict__ hi, __nv_bfloat16* __restrict__ lo)
{
    const int b = blockIdx.x;
    int si = 0;
    #pragma unroll 1
    for (int j = 1; j < t.nseg; j++) if (b >= t.s[j].blk0) si = j;
    const WSeg sg = t.s[si];
    const int i = (b - sg.blk0) * 256 + threadIdx.x;
    if (i >= sg.t8) return;
    const int e = i * 8;
    const int k = e / sg.Nsrc, n = e - k * sg.Nsrc;   // n multiple of 8
    const float4 v0 = *(const float4*)(sg.W + e);
    const float4 v1 = *(const float4*)(sg.W + e + 4);
    uint4 hw, lw;
    split2(v0.x, v0.y, hw.x, lw.x);
    split2(v0.z, v0.w, hw.y, lw.y);
    split2(v1.x, v1.y, hw.z, lw.z);
    split2(v1.z, v1.w, hw.w, lw.w);
    const int col = sg.grp ? (((n >> 3) << 4) + sg.c0) : (sg.c0 + n);
    const size_t d = sg.dstoff + (size_t)k * sg.P + col;
    *(uint4*)(hi + d) = hw;
    *(uint4*)(lo + d) = lw;
}

// ============ HMMA GEMM: bf16 hi/lo operands, 3-stage cp.async ===============
#define A_PITCH 80
#define B_PITCH 272
#define A_TB    (128 * A_PITCH)
#define B_TB    (32 * B_PITCH)
#define STAGE_B (2 * A_TB + 2 * B_TB)  // 37888
#define HG_SMEM (3 * STAGE_B)          // 113664

__global__ void __launch_bounds__(256, 2)
hgemm_kernel(const __nv_bfloat16* __restrict__ Ahi,
             const __nv_bfloat16* __restrict__ Alo,
             const __nv_bfloat16* __restrict__ Bhi,
             const __nv_bfloat16* __restrict__ Blo,
             const float* __restrict__ bias,
             const float* __restrict__ res,
             float* __restrict__ C,
             __nv_bfloat16* __restrict__ Chi,
             __nv_bfloat16* __restrict__ Clo,
             int M, int N, int K, int Ap, int silu_mode)
{
    extern __shared__ char sm[];
    const uint32_t smb = smem_u32(sm);

    const int tid  = threadIdx.x;
    const int wid  = tid >> 5, lane = tid & 31;
    const int wm   = wid >> 2;
    const int wn   = wid & 3;
    const int m0 = blockIdx.y * 128, n0 = blockIdx.x * 128;
    const int nc = K >> 5;

    auto cpAB = [&](int c, int s) {
        const uint32_t stA = smb + s * STAGE_B;
        #pragma unroll
        for (int i = 0; i < 4; i++) {
            const int idx  = tid + i * 256;
            const int tile = idx >> 9;
            const int r    = (idx >> 2) & 127;
            const int g    = idx & 3;
            const __nv_bfloat16* src =
                (tile ? Alo : Ahi) + (size_t)(m0 + r) * Ap + c * 32 + g * 8;
            cp_async16(stA + tile * A_TB + r * A_PITCH + g * 16, src);
        }
        const uint32_t stB = stA + 2 * A_TB;
        #pragma unroll
        for (int i = 0; i < 4; i++) {
            const int idx  = tid + i * 256;
            const int tile = idx >> 9;
            const int r    = (idx >> 4) & 31;
            const int g    = idx & 15;
            const __nv_bfloat16* src =
                (tile ? Blo : Bhi) + (size_t)(c * 32 + r) * N + n0 + g * 8;
            cp_async16(stB + tile * B_TB + r * B_PITCH + g * 16, src);
        }
        cp_commit();
    };

    float acc[4][4][4];
    #pragma unroll
    for (int a = 0; a < 4; a++)
        #pragma unroll
        for (int b = 0; b < 4; b++)
            #pragma unroll
            for (int r = 0; r < 4; r++) acc[a][b][r] = 0.f;

    cpAB(0, 0);
    if (nc > 1) cpAB(1, 1);

    for (int c = 0; c < nc; c++) {
        if (c == nc - 1) cp_wait<0>(); else cp_wait<1>();
        __syncthreads();
        if (c + 2 < nc) cpAB(c + 2, (c + 2) % 3);

        const uint32_t stage = smb + (c % 3) * STAGE_B;
        const uint32_t sAh = stage, sAl = stage + A_TB;
        const uint32_t sBh = stage + 2 * A_TB, sBl = sBh + B_TB;

        #pragma unroll
        for (int ks = 0; ks < 2; ks++) {
            uint32_t ah[4][4], al[4][4];
            const uint32_t acb = ks * 32 + ((lane >> 4) * 16);
            #pragma unroll
            for (int mt = 0; mt < 4; mt++) {
                const uint32_t ro = (wm * 64 + mt * 16 + (lane & 15)) * A_PITCH + acb;
                ldm_x4(ah[mt], sAh + ro);
                ldm_x4(al[mt], sAl + ro);
            }
            const uint32_t brow16 = (ks * 16 + (lane & 15)) * B_PITCH;
            #pragma unroll
            for (int nt = 0; nt < 4; nt++) {
                const uint32_t co = (wn * 32 + nt * 8) * 2;
                uint32_t bh[2], bl[2];
                ldm_x2_trans(bh, sBh + brow16 + co);
                ldm_x2_trans(bl, sBl + brow16 + co);
                #pragma unroll
                for (int mt = 0; mt < 4; mt++) {
                    mma_bf16(acc[mt][nt], ah[mt], bh);
                    mma_bf16(acc[mt][nt], ah[mt], bl);
                    mma_bf16(acc[mt][nt], al[mt], bh);
                }
            }
        }
    }

    if (silu_mode) {
        const int No = N >> 1;
        #pragma unroll
        for (int mt = 0; mt < 4; mt++) {
            #pragma unroll
            for (int np = 0; np < 2; np++) {
                const int nt = np * 2;
                const int col1 = n0 + wn * 32 + nt * 8 + (lane & 3) * 2;
                const int nf = ((col1 >> 4) << 3) + (col1 & 7);
                #pragma unroll
                for (int hh = 0; hh < 2; hh++) {
                    const int row = m0 + wm * 64 + mt * 16 + (lane >> 2) + hh * 8;
                    float v0, v1;
                    {
                        const float a = acc[mt][nt][hh * 2];
                        v0 = (a / (1.0f + __expf(-a))) * acc[mt][nt + 1][hh * 2];
                        const float b = acc[mt][nt][hh * 2 + 1];
                        v1 = (b / (1.0f + __expf(-b))) * acc[mt][nt + 1][hh * 2 + 1];
                    }
                    uint32_t hw, lw;
                    split2(v0, v1, hw, lw);
                    const size_t off = (size_t)row * No + nf;
                    *(uint32_t*)(Chi + off) = hw;
                    *(uint32_t*)(Clo + off) = lw;
                }
            }
        }
    } else {
        #pragma unroll
        for (int mt = 0; mt < 4; mt++) {
            #pragma unroll
            for (int nt = 0; nt < 4; nt++) {
                const int col = n0 + wn * 32 + nt * 8 + (lane & 3) * 2;
                float bv0 = 0.f, bv1 = 0.f;
                if (bias) { bv0 = bias[col]; bv1 = bias[col + 1]; }
                #pragma unroll
                for (int hh = 0; hh < 2; hh++) {
                    const int row = m0 + wm * 64 + mt * 16 + (lane >> 2) + hh * 8;
                    float v0 = acc[mt][nt][hh * 2]     + bv0;
                    float v1 = acc[mt][nt][hh * 2 + 1] + bv1;
                    const size_t off = (size_t)row * N + col;
                    if (res) { v0 += res[off]; v1 += res[off + 1]; }
                    C[off]     = v0;
                    C[off + 1] = v1;
                }
            }
        }
    }
}

// ======================= RMSNorm (bf16 hi/lo output) =========================
__global__ void rmsnorm_kernel(const float* __restrict__ x,
                               const float* __restrict__ w,
                               __nv_bfloat16* __restrict__ ohi,
                               __nv_bfloat16* __restrict__ olo)
{
    const int row = blockIdx.x;
    const float* xr = x + (size_t)row * DMODEL;
    float s = 0.f;
    for (int i = threadIdx.x; i < DMODEL; i += 256) { float v = xr[i]; s += v * v; }
    #pragma unroll
    for (int off = 16; off; off >>= 1) s += __shfl_down_sync(0xffffffffu, s, off);
    __shared__ float red[8];
    const int warp = threadIdx.x >> 5, lane = threadIdx.x & 31;
    if (lane == 0) red[warp] = s;
    __syncthreads();
    if (warp == 0) {
        float t = (lane < 8) ? red[lane] : 0.f;
        #pragma unroll
        for (int off = 4; off; off >>= 1) t += __shfl_down_sync(0xffu, t, off);
        if (lane == 0) red[0] = t;
    }
    __syncthreads();
    const float inv = rsqrtf(red[0] * (1.0f / DMODEL) + 1e-5f);
    for (int i = threadIdx.x * 2; i < DMODEL; i += 512) {
        const float v0 = xr[i] * inv * w[i];
        const float v1 = xr[i + 1] * inv * w[i + 1];
        uint32_t hw, lw;
        split2(v0, v1, hw, lw);
        const size_t d = (size_t)row * DMODEL + i;
        *(uint32_t*)(ohi + d) = hw;
        *(uint32_t*)(olo + d) = lw;
    }
}

// ======================= MMA attention (FA2-style) ===========================
// CTA = (64 q, head). 128 threads, 4 warps, each warp 16 q rows.
// K-window chunks of 64; QK^T and PV via bf16 hi/lo 3-pass HMMA.
#define AP 72                      // padded tile pitch (elems); 144 B rows
#define ATILE (64 * AP * 2)        // 9216 B per (hi or lo) tile
#define ATTN_SMEM (6 * ATILE + 512)

__global__ void __launch_bounds__(128, 4)
attn_kernel(const float* __restrict__ qkv,
            const int* __restrict__ doc_id,
            const int* __restrict__ tok_id,
            const float* __restrict__ ct,
            const float* __restrict__ st,
            __nv_bfloat16* __restrict__ ohi,
            __nv_bfloat16* __restrict__ olo)
{
    extern __shared__ char smc[];
    const uint32_t smb = smem_u32(smc);
    const uint32_t smQh = smb, smQl = smb + ATILE;
    const uint32_t smKh = smb + 2 * ATILE, smKl = smb + 3 * ATILE;
    const uint32_t smVh = smb + 4 * ATILE, smVl = smb + 5 * ATILE;
    int* docs = (int*)(smc + 6 * ATILE);
    int* toks = docs + 64;

    const int q0 = blockIdx.x * 64;
    const int h  = blockIdx.y;
    const int tid = threadIdx.x;
    const int wid = tid >> 5, lane = tid & 31;

    // ---- load Q tile: rope + hi/lo split (8 iters, 2-dim pairs) ----
    #pragma unroll
    for (int j = 0; j < 8; j++) {
        const int e = j * 128 + tid;
        const int r = e >> 4, i2 = (e & 15) * 2;
        const int s = q0 + r;
        const size_t base = (size_t)s * 3072 + h * HDIM;
        const float c0 = ct[s * 32 + i2],     s0 = st[s * 32 + i2];
        const float c1 = ct[s * 32 + i2 + 1], s1 = st[s * 32 + i2 + 1];
        const float xa = qkv[base + i2],      xb = qkv[base + i2 + 1];
        const float ya = qkv[base + 32 + i2], yb = qkv[base + 33 + i2];
        uint32_t hw, lw;
        split2(xa * c0 - ya * s0, xb * c1 - yb * s1, hw, lw);
        *(uint32_t*)(smc + (smQh - smb) + (r * AP + i2) * 2) = hw;
        *(uint32_t*)(smc + (smQl - smb) + (r * AP + i2) * 2) = lw;
        split2(xa * s0 + ya * c0, xb * s1 + yb * c1, hw, lw);
        *(uint32_t*)(smc + (smQh - smb) + (r * AP + 32 + i2) * 2) = hw;
        *(uint32_t*)(smc + (smQl - smb) + (r * AP + 32 + i2) * 2) = lw;
    }

    const int gq0 = q0 + wid * 16 + (lane >> 2);   // row for c0,c1
    const int myDoc0 = doc_id[gq0],     myTok0 = tok_id[gq0];
    const int myDoc1 = doc_id[gq0 + 8], myTok1 = tok_id[gq0 + 8];

    __syncthreads();

    // hoist Q fragments (constant across chunks)
    uint32_t qh[4][4], ql[4][4];
    #pragma unroll
    for (int sl = 0; sl < 4; sl++) {
        const uint32_t ro = (wid * 16 + (lane & 15)) * 144 +
                            sl * 32 + ((lane >> 4) * 16);
        ldm_x4(qh[sl], smQh + ro);
        ldm_x4(ql[sl], smQl + ro);
    }

    float mr0 = -1e29f, mr1 = -1e29f, l0 = 0.f, l1 = 0.f;
    float Oc[8][4];
    #pragma unroll
    for (int t = 0; t < 8; t++)
        #pragma unroll
        for (int r = 0; r < 4; r++) Oc[t][r] = 0.f;

    for (int ch = 0; ch < 5; ch++) {
        const int kb = q0 - 128 + ch * 64;
        __syncthreads();
        // ---- load K (rope) + V, hi/lo split ----
        #pragma unroll
        for (int j = 0; j < 8; j++) {
            const int e = j * 128 + tid;
            const int r = e >> 4, i2 = (e & 15) * 2;
            const int kg = kb + r;
            const bool in = (kg >= 0) & (kg < SLEN);
            const int ks = in ? kg : 0;
            const size_t base = (size_t)ks * 3072 + h * HDIM;
            const float c0 = ct[ks * 32 + i2],     s0 = st[ks * 32 + i2];
            const float c1 = ct[ks * 32 + i2 + 1], s1 = st[ks * 32 + i2 + 1];
            float xa = qkv[base + 1024 + i2], xb = qkv[base + 1025 + i2];
            float ya = qkv[base + 1056 + i2], yb = qkv[base + 1057 + i2];
            uint32_t hw, lw;
            float k1a = in ? (xa * c0 - ya * s0) : 0.f;
            float k1b = in ? (xb * c1 - yb * s1) : 0.f;
            float k2a = in ? (xa * s0 + ya * c0) : 0.f;
            float k2b = in ? (xb * s1 + yb * c1) : 0.f;
            split2(k1a, k1b, hw, lw);
            *(uint32_t*)(smc + (smKh - smb) + (r * AP + i2) * 2) = hw;
            *(uint32_t*)(smc + (smKl - smb) + (r * AP + i2) * 2) = lw;
            split2(k2a, k2b, hw, lw);
            *(uint32_t*)(smc + (smKh - smb) + (r * AP + 32 + i2) * 2) = hw;
            *(uint32_t*)(smc + (smKl - smb) + (r * AP + 32 + i2) * 2) = lw;
            const float va = in ? qkv[base + 2048 + i2] : 0.f;
            const float vb = in ? qkv[base + 2049 + i2] : 0.f;
            const float vc = in ? qkv[base + 2080 + i2] : 0.f;
            const float vd = in ? qkv[base + 2081 + i2] : 0.f;
            split2(va, vb, hw, lw);
            *(uint32_t*)(smc + (smVh - smb) + (r * AP + i2) * 2) = hw;
            *(uint32_t*)(smc + (smVl - smb) + (r * AP + i2) * 2) = lw;
            split2(vc, vd, hw, lw);
            *(uint32_t*)(smc + (smVh - smb) + (r * AP + 32 + i2) * 2) = hw;
            *(uint32_t*)(smc + (smVl - smb) + (r * AP + 32 + i2) * 2) = lw;
        }
        if (tid < 64) {
            const int kg = kb + tid;
            const bool in = (kg >= 0) & (kg < SLEN);
            docs[tid] = in ? doc_id[kg] : -1;
            toks[tid] = in ? tok_id[kg] : 0;
        }
        __syncthreads();

        // ---- S = Q K^T (3-pass) ----
        float sc[8][4];
        #pragma unroll
        for (int t = 0; t < 8; t++)
            #pragma unroll
            for (int r = 0; r < 4; r++) sc[t][r] = 0.f;
        #pragma unroll
        for (int sl = 0; sl < 4; sl++) {
            #pragma unroll
            for (int nt = 0; nt < 8; nt++) {
                const uint32_t ro = (nt * 8 + (lane & 7)) * 144 +
                                    sl * 32 + (((lane >> 3) & 1) * 16);
                uint32_t bh[2], bl[2];
                ldm_x2(bh, smKh + ro);
                ldm_x2(bl, smKl + ro);
                mma_bf16(sc[nt], qh[sl], bh);
                mma_bf16(sc[nt], qh[sl], bl);
                mma_bf16(sc[nt], ql[sl], bh);
            }
        }

        // ---- mask + scale ----
        #pragma unroll
        for (int nt = 0; nt < 8; nt++) {
            const int kl = nt * 8 + 2 * (lane & 3);
            const int d0 = docs[kl], t0 = toks[kl];
            const int d1 = docs[kl + 1], t1 = toks[kl + 1];
            const bool ok00 = (d0 == myDoc0) && (abs(t0 - myTok0) < 128);
            const bool ok01 = (d1 == myDoc0) && (abs(t1 - myTok0) < 128);
            const bool ok10 = (d0 == myDoc1) && (abs(t0 - myTok1) < 128);
            const bool ok11 = (d1 == myDoc1) && (abs(t1 - myTok1) < 128);
            sc[nt][0] = ok00 ? sc[nt][0] * 0.125f : -1e30f;
            sc[nt][1] = ok01 ? sc[nt][1] * 0.125f : -1e30f;
            sc[nt][2] = ok10 ? sc[nt][2] * 0.125f : -1e30f;
            sc[nt][3] = ok11 ? sc[nt][3] * 0.125f : -1e30f;
        }

        // ---- online softmax (rows r and r+8) ----
        float cm0 = -1e30f, cm1 = -1e30f;
        #pragma unroll
        for (int t = 0; t < 8; t++) {
            cm0 = fmaxf(cm0, fmaxf(sc[t][0], sc[t][1]));
            cm1 = fmaxf(cm1, fmaxf(sc[t][2], sc[t][3]));
        }
        cm0 = fmaxf(cm0, __shfl_xor_sync(0xffffffffu, cm0, 1));
        cm0 = fmaxf(cm0, __shfl_xor_sync(0xffffffffu, cm0, 2));
        cm1 = fmaxf(cm1, __shfl_xor_sync(0xffffffffu, cm1, 1));
        cm1 = fmaxf(cm1, __shfl_xor_sync(0xffffffffu, cm1, 2));
        const float mn0 = fmaxf(mr0, cm0), mn1 = fmaxf(mr1, cm1);
        const float es0 = __expf(mr0 - mn0), es1 = __expf(mr1 - mn1);
        mr0 = mn0; mr1 = mn1;
        l0 *= es0; l1 *= es1;
        #pragma unroll
        for (int t = 0; t < 8; t++) {
            Oc[t][0] *= es0; Oc[t][1] *= es0;
            Oc[t][2] *= es1; Oc[t][3] *= es1;
        }
        float rs0 = 0.f, rs1 = 0.f;
        #pragma unroll
        for (int t = 0; t < 8; t++) {
            sc[t][0] = __expf(sc[t][0] - mn0);
            sc[t][1] = __expf(sc[t][1] - mn0);
            sc[t][2] = __expf(sc[t][2] - mn1);
            sc[t][3] = __expf(sc[t][3] - mn1);
            rs0 += sc[t][0] + sc[t][1];
            rs1 += sc[t][2] + sc[t][3];
        }
        rs0 += __shfl_xor_sync(0xffffffffu, rs0, 1);
        rs0 += __shfl_xor_sync(0xffffffffu, rs0, 2);
        rs1 += __shfl_xor_sync(0xffffffffu, rs1, 1);
        rs1 += __shfl_xor_sync(0xffffffffu, rs1, 2);
        l0 += rs0; l1 += rs1;

        // ---- O += P V (3-pass), P from acc layout identity ----
        #pragma unroll
        for (int j = 0; j < 4; j++) {
            uint32_t ph[4], pl[4];
            split2(sc[2 * j][0],     sc[2 * j][1],     ph[0], pl[0]);
            split2(sc[2 * j][2],     sc[2 * j][3],     ph[1], pl[1]);
            split2(sc[2 * j + 1][0], sc[2 * j + 1][1], ph[2], pl[2]);
            split2(sc[2 * j + 1][2], sc[2 * j + 1][3], ph[3], pl[3]);
            #pragma unroll
            for (int t = 0; t < 8; t++) {
                const uint32_t ro = (j * 16 + (lane & 15)) * 144 + t * 16;
                uint32_t vh[2], vl[2];
                ldm_x2_trans(vh, smVh + ro);
                ldm_x2_trans(vl, smVl + ro);
                mma_bf16(Oc[t], ph, vh);
                mma_bf16(Oc[t], pl, vh);
                mma_bf16(Oc[t], ph, vl);
            }
        }
    }

    // ---- epilogue ----
    const float inv0 = 1.f / l0, inv1 = 1.f / l1;
    #pragma unroll
    for (int t = 0; t < 8; t++) {
        const int d = t * 8 + 2 * (lane & 3);
        uint32_t hw, lw;
        const size_t b0 = (size_t)gq0 * DMODEL + h * HDIM + d;
        split2(Oc[t][0] * inv0, Oc[t][1] * inv0, hw, lw);
        *(uint32_t*)(ohi + b0) = hw;
        *(uint32_t*)(olo + b0) = lw;
        const size_t b1 = b0 + (size_t)8 * DMODEL;
        split2(Oc[t][2] * inv1, Oc[t][3] * inv1, hw, lw);
        *(uint32_t*)(ohi + b1) = hw;
        *(uint32_t*)(olo + b1) = lw;
    }
}

// ======================= launch ==============================================
static void run_gemm(const __nv_bfloat16* Ahi, const __nv_bfloat16* Alo,
                     const __nv_bfloat16* Bhi, const __nv_bfloat16* Blo,
                     const float* bias, const float* res, float* C,
                     __nv_bfloat16* Chi, __nv_bfloat16* Clo,
                     int M, int N, int K, int Ap, int silu = 0)
{
    dim3 g(N / 128, M / 128);
    hgemm_kernel<<<g, 256, HG_SMEM>>>(Ahi, Alo, Bhi, Blo, bias, res, C, Chi, Clo,
                                      M, N, K, Ap, silu);
}

static int add_seg(WTab& t, int& blk, const float* W, unsigned dstoff,
                   int K, int Nsrc, int P, int c0, int grp)
{
    const int t8 = K * Nsrc / 8;
    WSeg& s = t.s[t.nseg++];
    s.W = W; s.dstoff = dstoff; s.Nsrc = Nsrc; s.P = P;
    s.c0 = c0; s.grp = grp; s.t8 = t8; s.blk0 = blk;
    blk += (t8 + 255) / 256;
    return blk;
}

extern "C" void kernel_launch(void* const* d_in, const int* in_sizes, int n_in,
                              void* d_out, int out_size)
{
    const float* x           = (const float*)d_in[0];
    const float* emb_w       = (const float*)d_in[1];
    const float* emb_b       = (const float*)d_in[2];
    const float* wq          = (const float*)d_in[3];
    const float* wk          = (const float*)d_in[4];
    const float* wv          = (const float*)d_in[5];
    const float* wo          = (const float*)d_in[6];
    const float* attn_norm_w = (const float*)d_in[7];
    const float* ffn_norm_w  = (const float*)d_in[8];
    const float* w1          = (const float*)d_in[9];
    const float* w2          = (const float*)d_in[10];
    const float* w3          = (const float*)d_in[11];
    const float* out_norm_w  = (const float*)d_in[12];
    const float* out_w       = (const float*)d_in[13];
    const int*   doc_id      = (const int*)d_in[14];
    const int*   tok_id      = (const int*)d_in[15];
    float* out = (float*)d_out;

    cudaFuncSetAttribute(hgemm_kernel,
                         cudaFuncAttributeMaxDynamicSharedMemorySize, HG_SMEM);
    cudaFuncSetAttribute(attn_kernel,
                         cudaFuncAttributeMaxDynamicSharedMemorySize, ATTN_SMEM);

    float *h, *qkv, *ct, *st;
    __nv_bfloat16 *whi, *wlo, *hnh, *hnl, *oh, *ol, *fh, *fl, *xh, *xl;
    cudaGetSymbolAddress((void**)&h,   g_h);
    cudaGetSymbolAddress((void**)&qkv, g_qkv);
    cudaGetSymbolAddress((void**)&ct,  g_ct);
    cudaGetSymbolAddress((void**)&st,  g_st);
    cudaGetSymbolAddress((void**)&whi, g_whi);
    cudaGetSymbolAddress((void**)&wlo, g_wlo);
    cudaGetSymbolAddress((void**)&hnh, g_hn_hi);
    cudaGetSymbolAddress((void**)&hnl, g_hn_lo);
    cudaGetSymbolAddress((void**)&oh,  g_o_hi);
    cudaGetSymbolAddress((void**)&ol,  g_o_lo);
    cudaGetSymbolAddress((void**)&fh,  g_f_hi);
    cudaGetSymbolAddress((void**)&fl,  g_f_lo);
    cudaGetSymbolAddress((void**)&xh,  g_x_hi);
    cudaGetSymbolAddress((void**)&xl,  g_x_lo);

    // launch 0: trig table + x split
    init_kernel<<<(SLEN * 32 + SLEN * IND / 4 + 255) / 256, 256>>>(
        tok_id, x, ct, st, xh, xl);

    // launches 1,2: batched weight split
    for (int halfi = 0; halfi < 2; halfi++) {
        WTab t;
        t.nseg = 0;
        int blk = 0;
        if (halfi == 0)
            add_seg(t, blk, emb_w, 0, IND, DMODEL, DMODEL, 0, 0);
        for (int l = halfi * 2; l < halfi * 2 + 2; l++) {
            const unsigned lb = OFF_L + (unsigned)l * LSTR;
            const size_t wqo = (size_t)l * DMODEL * DMODEL;
            const size_t wfo = (size_t)l * DMODEL * FFND;
            add_seg(t, blk, wq + wqo, lb,            DMODEL, DMODEL, 3072, 0,    0);
            add_seg(t, blk, wk + wqo, lb,            DMODEL, DMODEL, 3072, 1024, 0);
            add_seg(t, blk, wv + wqo, lb,            DMODEL, DMODEL, 3072, 2048, 0);
            add_seg(t, blk, wo + wqo, lb + 3145728,  DMODEL, DMODEL, 1024, 0,    0);
            add_seg(t, blk, w1 + wfo, lb + 4194304,  DMODEL, FFND,   8192, 0,    1);
            add_seg(t, blk, w3 + wfo, lb + 4194304,  DMODEL, FFND,   8192, 8,    1);
            add_seg(t, blk, w2 + wfo, lb + 12582912, FFND,   DMODEL, 1024, 0,    0);
        }
        if (halfi == 1)
            add_seg(t, blk, out_w, OFF_OUT, DMODEL, OUTD, OUTD, 0, 0);
        wsplit_all<<<blk, 256>>>(t, whi, wlo);
    }

    // embedding
    run_gemm(xh, xl, whi, wlo, emb_b, nullptr, h, nullptr, nullptr,
             SLEN, DMODEL, IND, IND);

    for (int l = 0; l < NLAYER; l++) {
        const __nv_bfloat16* hb = whi + OFF_L + (size_t)l * LSTR;
        const __nv_bfloat16* lb = wlo + OFF_L + (size_t)l * LSTR;

        rmsnorm_kernel<<<SLEN, 256>>>(h, attn_norm_w + (size_t)l * DMODEL, hnh, hnl);
        run_gemm(hnh, hnl, hb, lb, nullptr, nullptr, qkv, nullptr, nullptr,
                 SLEN, 3072, DMODEL, DMODEL);
        attn_kernel<<<dim3(SLEN / 64, NH), 128, ATTN_SMEM>>>(qkv, doc_id, tok_id,
                                                             ct, st, oh, ol);
        run_gemm(oh, ol, hb + 3145728, lb + 3145728, nullptr, h, h, nullptr, nullptr,
                 SLEN, DMODEL, DMODEL, DMODEL);

        rmsnorm_kernel<<<SLEN, 256>>>(h, ffn_norm_w + (size_t)l * DMODEL, hnh, hnl);
        run_gemm(hnh, hnl, hb + 4194304, lb + 4194304, nullptr, nullptr,
                 nullptr, fh, fl, SLEN, 2 * FFND, DMODEL, DMODEL, 1);
        run_gemm(fh, fl, hb + 12582912, lb + 12582912, nullptr, h, h, nullptr, nullptr,
                 SLEN, DMODEL, FFND, FFND);
    }

    rmsnorm_kernel<<<SLEN, 256>>>(h, out_norm_w, hnh, hnl);
    run_gemm(hnh, hnl, whi + OFF_OUT, wlo + OFF_OUT, nullptr, nullptr, out,
             nullptr, nullptr, SLEN, OUTD, DMODEL, DMODEL);
}